// round 1
// baseline (speedup 1.0000x reference)
#include <cuda_runtime.h>

#define NN 20000
#define EE 320000
#define H 128
#define FIN 14
#define FOUT 9
#define NLAYERS 6
#define EDIM 3
#define TE 128      // edges per CTA tile
#define SA 132      // smem row stride (floats), 16B aligned, conflict-mitigating

// ---------------- device scratch (no allocations allowed) ----------------
__device__ float g_h[NN * H];
__device__ float g_agg[NN * H];
__device__ float g_deg[NN];
__device__ int   g_src[EE];
__device__ int   g_dst[EE];
__device__ int   g_is64;

__device__ __forceinline__ float silu_f(float x) {
    return x / (1.0f + __expf(-x));
}

// ---------------- dtype detection for edge_index (int32 vs int64) --------
__global__ void k_detect(const int* __restrict__ ei) {
    __shared__ int cnt;
    if (threadIdx.x == 0) cnt = 0;
    __syncthreads();
    int c = 0;
    // If int64 (little-endian, values < 2^31): every odd int32 word is 0.
    for (int i = threadIdx.x; i < 1024; i += 256)
        if (ei[2 * i + 1] != 0) c++;
    if (c) atomicAdd(&cnt, c);
    __syncthreads();
    if (threadIdx.x == 0) g_is64 = (cnt == 0) ? 1 : 0;
}

__global__ void k_zero() {
    int i = blockIdx.x * blockDim.x + threadIdx.x;
    if (i < NN * H) g_agg[i] = 0.0f;
    if (i < NN) g_deg[i] = 0.0f;
}

__global__ void k_convert(const void* __restrict__ ei) {
    int i = blockIdx.x * blockDim.x + threadIdx.x;
    if (i >= EE) return;
    int s, d;
    if (g_is64) {
        const long long* p = (const long long*)ei;
        s = (int)p[i];
        d = (int)p[EE + i];
    } else {
        const int* p = (const int*)ei;
        s = p[i];
        d = p[EE + i];
    }
    g_src[i] = s;
    g_dst[i] = d;
    atomicAdd(&g_deg[d], 1.0f);
}

// ---------------- encoder: h = (silu(x W1 + b1)) W2 + b2 -----------------
__global__ void k_encoder(const float* __restrict__ x,
                          const float* __restrict__ w1, const float* __restrict__ b1,
                          const float* __restrict__ w2, const float* __restrict__ b2) {
    int node = blockIdx.x;
    int j = threadIdx.x; // 128
    __shared__ float sx[FIN];
    __shared__ float sz[H];
    if (j < FIN) sx[j] = x[node * FIN + j];
    __syncthreads();
    float a = b1[j];
#pragma unroll
    for (int k = 0; k < FIN; k++) a += sx[k] * w1[k * H + j];
    sz[j] = silu_f(a);
    __syncthreads();
    float a2 = b2[j];
#pragma unroll 8
    for (int k = 0; k < H; k++) a2 += sz[k] * w2[k * H + j];
    g_h[node * H + j] = a2;
}

// ---------------- fused edge layer: gather -> MLP -> atomic scatter ------
// CTA: 256 threads, 128 edges. Thread (ty,tx) in 16x16 grid owns an 8x8
// sub-tile of the 128(edges) x 128(channels) output.
__global__ void __launch_bounds__(256, 2)
k_edge(const float* __restrict__ ea,
       const float* __restrict__ W1, const float* __restrict__ b1,
       const float* __restrict__ W2, const float* __restrict__ b2) {
    extern __shared__ float sm[];
    float* As = sm;                 // [32][SA]  feature k-tile, [k][edge]
    float* Bs = As + 32 * SA;       // [32][SA]  weight k-tile,  [k][col]
    float* Zs = Bs + 32 * SA;       // [128][SA] z1, [edge][ch]
    int* sDst = (int*)(Zs + 128 * SA);   // [TE]
    int* sSrc = sDst + TE;               // [TE]
    float* sEa = (float*)(sSrc + TE);    // [TE][3]

    const int tid = threadIdx.x;
    const int e0 = blockIdx.x * TE;
    const int tx = tid & 15;
    const int ty = tid >> 4;
    const int row0 = ty * 8;  // edge within tile
    const int col0 = tx * 8;  // output channel

    if (tid < TE) {
        sDst[tid] = g_dst[e0 + tid];
        sSrc[tid] = g_src[e0 + tid];
        sEa[tid * 3 + 0] = ea[(e0 + tid) * 3 + 0];
        sEa[tid * 3 + 1] = ea[(e0 + tid) * 3 + 1];
        sEa[tid * 3 + 2] = ea[(e0 + tid) * 3 + 2];
    }
    __syncthreads();

    float acc[8][8];
#pragma unroll
    for (int r = 0; r < 8; r++)
#pragma unroll
        for (int c = 0; c < 8; c++) acc[r][c] = 0.0f;

    // ---- GEMM1: k in [0,256): k<128 -> h[dst], else h[src]; 8 tiles of 32
    for (int t = 0; t < 8; t++) {
        const int koff = (t & 3) * 32;
        const int* nodes = (t < 4) ? sDst : sSrc;
        // load A tile (gather, float4 coalesced per node row), store transposed
#pragma unroll
        for (int it = 0; it < 4; ++it) {
            int i = tid + it * 256;       // i in [0,1024)
            int edge = i >> 3, seg = i & 7;
            const float4 v = *(const float4*)&g_h[nodes[edge] * H + koff + seg * 4];
            As[(seg * 4 + 0) * SA + edge] = v.x;
            As[(seg * 4 + 1) * SA + edge] = v.y;
            As[(seg * 4 + 2) * SA + edge] = v.z;
            As[(seg * 4 + 3) * SA + edge] = v.w;
        }
        // load B tile (plain copy)
#pragma unroll
        for (int it = 0; it < 4; ++it) {
            int i = tid + it * 256;
            int rowk = i >> 5, c4 = i & 31;
            *(float4*)&Bs[rowk * SA + c4 * 4] =
                *(const float4*)&W1[(t * 32 + rowk) * H + c4 * 4];
        }
        __syncthreads();
#pragma unroll 4
        for (int kk = 0; kk < 32; ++kk) {
            float4 a0 = *(const float4*)&As[kk * SA + row0];
            float4 a1 = *(const float4*)&As[kk * SA + row0 + 4];
            float4 bq0 = *(const float4*)&Bs[kk * SA + col0];
            float4 bq1 = *(const float4*)&Bs[kk * SA + col0 + 4];
            float av[8] = {a0.x, a0.y, a0.z, a0.w, a1.x, a1.y, a1.z, a1.w};
            float bv[8] = {bq0.x, bq0.y, bq0.z, bq0.w, bq1.x, bq1.y, bq1.z, bq1.w};
#pragma unroll
            for (int r = 0; r < 8; r++)
#pragma unroll
                for (int c = 0; c < 8; c++) acc[r][c] += av[r] * bv[c];
        }
        __syncthreads();
    }

    // ---- K tail: edge_attr rows k = 256..258
#pragma unroll
    for (int j = 0; j < 3; j++) {
        float bv[8];
#pragma unroll
        for (int c = 0; c < 8; c++) bv[c] = W1[(256 + j) * H + col0 + c];
#pragma unroll
        for (int r = 0; r < 8; r++) {
            float aval = sEa[(row0 + r) * 3 + j];
#pragma unroll
            for (int c = 0; c < 8; c++) acc[r][c] += aval * bv[c];
        }
    }

    // ---- epilogue 1: +b1, SiLU, stash z1 in smem, reset acc
    {
        float bb[8];
#pragma unroll
        for (int c = 0; c < 8; c++) bb[c] = b1[col0 + c];
#pragma unroll
        for (int r = 0; r < 8; r++) {
            float zv[8];
#pragma unroll
            for (int c = 0; c < 8; c++) {
                zv[c] = silu_f(acc[r][c] + bb[c]);
                acc[r][c] = 0.0f;
            }
            *(float4*)&Zs[(row0 + r) * SA + col0] = make_float4(zv[0], zv[1], zv[2], zv[3]);
            *(float4*)&Zs[(row0 + r) * SA + col0 + 4] = make_float4(zv[4], zv[5], zv[6], zv[7]);
        }
    }
    __syncthreads();

    // ---- GEMM2: m = z1 @ W2 (K=128, 4 tiles of 32)
    for (int t2 = 0; t2 < 4; t2++) {
#pragma unroll
        for (int it = 0; it < 4; ++it) {
            int i = tid + it * 256;
            int rowk = i >> 5, c4 = i & 31;
            *(float4*)&Bs[rowk * SA + c4 * 4] =
                *(const float4*)&W2[(t2 * 32 + rowk) * H + c4 * 4];
        }
        __syncthreads();
#pragma unroll 4
        for (int kk = 0; kk < 32; ++kk) {
            float4 bq0 = *(const float4*)&Bs[kk * SA + col0];
            float4 bq1 = *(const float4*)&Bs[kk * SA + col0 + 4];
            float bv[8] = {bq0.x, bq0.y, bq0.z, bq0.w, bq1.x, bq1.y, bq1.z, bq1.w};
            float av[8];
#pragma unroll
            for (int r = 0; r < 8; r++)
                av[r] = Zs[(row0 + r) * SA + t2 * 32 + kk]; // broadcast, conflict-free
#pragma unroll
            for (int r = 0; r < 8; r++)
#pragma unroll
                for (int c = 0; c < 8; c++) acc[r][c] += av[r] * bv[c];
        }
        __syncthreads();
    }

    // ---- epilogue 2: +b2 per message, atomic scatter-add into agg[dst]
    {
        float bb[8];
#pragma unroll
        for (int c = 0; c < 8; c++) bb[c] = b2[col0 + c];
#pragma unroll
        for (int r = 0; r < 8; r++) {
            float* base = &g_agg[sDst[row0 + r] * H + col0];
#pragma unroll
            for (int c = 0; c < 8; c++) atomicAdd(base + c, acc[r][c] + bb[c]);
        }
    }
}

// ---------------- residual update: h += agg/deg; agg = 0 -----------------
__global__ void k_update() {
    int i = blockIdx.x * blockDim.x + threadIdx.x;
    if (i >= NN * H) return;
    float a = g_agg[i];
    g_agg[i] = 0.0f;
    g_h[i] += a / fmaxf(g_deg[i >> 7], 1.0f);
}

// ---------------- decoder ------------------------------------------------
__global__ void k_decoder(const float* __restrict__ w1, const float* __restrict__ b1,
                          const float* __restrict__ w2, const float* __restrict__ b2,
                          const float* __restrict__ w3, const float* __restrict__ b3,
                          float* __restrict__ out) {
    int node = blockIdx.x;
    int j = threadIdx.x; // 128
    __shared__ float sh[H];
    __shared__ float st1[H];
    __shared__ float st2[64];
    sh[j] = g_h[node * H + j];
    __syncthreads();
    float a = b1[j];
#pragma unroll 8
    for (int k = 0; k < H; k++) a += sh[k] * w1[k * H + j];
    st1[j] = silu_f(a);
    __syncthreads();
    if (j < 64) {
        float a2 = b2[j];
#pragma unroll 8
        for (int k = 0; k < H; k++) a2 += st1[k] * w2[k * 64 + j];
        st2[j] = silu_f(a2);
    }
    __syncthreads();
    if (j < FOUT) {
        float a3 = b3[j];
#pragma unroll
        for (int k = 0; k < 64; k++) a3 += st2[k] * w3[k * FOUT + j];
        out[node * FOUT + j] = a3;
    }
}

// ---------------- launch -------------------------------------------------
extern "C" void kernel_launch(void* const* d_in, const int* in_sizes, int n_in,
                              void* d_out, int out_size) {
    const float* x      = (const float*)d_in[0];
    const void*  ei     = d_in[1];
    const float* ea     = (const float*)d_in[2];
    const float* enc_w1 = (const float*)d_in[3];
    const float* enc_b1 = (const float*)d_in[4];
    const float* enc_w2 = (const float*)d_in[5];
    const float* enc_b2 = (const float*)d_in[6];
    const float* conv_w1 = (const float*)d_in[7];   // (L,259,128)
    const float* conv_b1 = (const float*)d_in[8];   // (L,128)
    const float* conv_w2 = (const float*)d_in[9];   // (L,128,128)
    const float* conv_b2 = (const float*)d_in[10];  // (L,128)
    const float* dec_w1 = (const float*)d_in[11];
    const float* dec_b1 = (const float*)d_in[12];
    const float* dec_w2 = (const float*)d_in[13];
    const float* dec_b2 = (const float*)d_in[14];
    const float* dec_w3 = (const float*)d_in[15];
    const float* dec_b3 = (const float*)d_in[16];

    const int SMEM = (32 * SA * 2 + 128 * SA) * (int)sizeof(float)
                   + 2 * TE * (int)sizeof(int) + TE * 3 * (int)sizeof(float);
    cudaFuncSetAttribute(k_edge, cudaFuncAttributeMaxDynamicSharedMemorySize, SMEM);

    k_detect<<<1, 256>>>((const int*)ei);
    k_zero<<<(NN * H + 255) / 256, 256>>>();
    k_convert<<<(EE + 255) / 256, 256>>>(ei);
    k_encoder<<<NN, H>>>(x, enc_w1, enc_b1, enc_w2, enc_b2);

    for (int l = 0; l < NLAYERS; l++) {
        k_edge<<<EE / TE, 256, SMEM>>>(ea,
                                       conv_w1 + (size_t)l * 259 * H,
                                       conv_b1 + (size_t)l * H,
                                       conv_w2 + (size_t)l * H * H,
                                       conv_b2 + (size_t)l * H);
        k_update<<<(NN * H + 255) / 256, 256>>>();
    }

    k_decoder<<<NN, H>>>(dec_w1, dec_b1, dec_w2, dec_b2, dec_w3, dec_b3, (float*)d_out);
}

// round 3
// speedup vs baseline: 2.0282x; 2.0282x over previous
#include <cuda_runtime.h>

#define NN 20000
#define EE 320000
#define H 128
#define FIN 14
#define FOUT 9
#define NLAYERS 6
#define TE 128      // edges per CTA tile
#define SA 132      // smem row stride (floats)

// ---------------- device scratch (no allocations allowed) ----------------
__device__ float g_h[NN * H];
__device__ float g_agg[NN * H];
__device__ float g_P[NN * 256];       // per-node projections [Pa | Pb]
__device__ float g_invdeg[NN];
__device__ int   g_src[EE];
__device__ int   g_dst[EE];
__device__ int   g_cnt[NN];
__device__ int   g_off[NN + 1];
__device__ int   g_ssrc[EE];          // dst-sorted
__device__ int   g_sdst[EE];
__device__ int   g_sperm[EE];
__device__ int   g_is64;

__device__ __forceinline__ float silu_f(float x) {
    return x / (1.0f + __expf(-x));
}

// ---------------- dtype detection for edge_index (int32 vs int64) --------
__global__ void k_detect(const int* __restrict__ ei) {
    __shared__ int cnt;
    if (threadIdx.x == 0) cnt = 0;
    __syncthreads();
    int c = 0;
    for (int i = threadIdx.x; i < 1024; i += 256)
        if (ei[2 * i + 1] != 0) c++;
    if (c) atomicAdd(&cnt, c);
    __syncthreads();
    if (threadIdx.x == 0) g_is64 = (cnt == 0) ? 1 : 0;
}

__global__ void k_init() {
    int i = blockIdx.x * blockDim.x + threadIdx.x;
    if (i < NN * H) g_agg[i] = 0.0f;
    if (i < NN) g_cnt[i] = 0;
}

__global__ void k_convert(const void* __restrict__ ei) {
    int i = blockIdx.x * blockDim.x + threadIdx.x;
    if (i >= EE) return;
    int s, d;
    if (g_is64) {
        const long long* p = (const long long*)ei;
        s = (int)p[i];
        d = (int)p[EE + i];
    } else {
        const int* p = (const int*)ei;
        s = p[i];
        d = p[EE + i];
    }
    g_src[i] = s;
    g_dst[i] = d;
    atomicAdd(&g_cnt[d], 1);
}

__global__ void k_invdeg() {
    int i = blockIdx.x * blockDim.x + threadIdx.x;
    if (i < NN) g_invdeg[i] = 1.0f / fmaxf((float)g_cnt[i], 1.0f);
}

// exclusive prefix sum of g_cnt -> g_off, reset g_cnt to 0 (cursor)
__global__ void k_scan() {
    __shared__ int buf[1024];
    __shared__ int carry;
    if (threadIdx.x == 0) carry = 0;
    __syncthreads();
    for (int base = 0; base < NN; base += 1024) {
        int i = base + threadIdx.x;
        int v = (i < NN) ? g_cnt[i] : 0;
        buf[threadIdx.x] = v;
        __syncthreads();
        for (int s = 1; s < 1024; s <<= 1) {
            int t = (threadIdx.x >= s) ? buf[threadIdx.x - s] : 0;
            __syncthreads();
            buf[threadIdx.x] += t;
            __syncthreads();
        }
        if (i < NN) {
            g_off[i] = carry + buf[threadIdx.x] - v;
            g_cnt[i] = 0;
        }
        __syncthreads();
        if (threadIdx.x == 1023) carry += buf[1023];
        __syncthreads();
    }
    if (threadIdx.x == 0) g_off[NN] = EE;
}

__global__ void k_scatter() {
    int e = blockIdx.x * blockDim.x + threadIdx.x;
    if (e >= EE) return;
    int d = g_dst[e];
    int pos = g_off[d] + atomicAdd(&g_cnt[d], 1);
    g_ssrc[pos] = g_src[e];
    g_sdst[pos] = d;
    g_sperm[pos] = e;
}

// ---------------- encoder ------------------------------------------------
__global__ void k_encoder(const float* __restrict__ x,
                          const float* __restrict__ w1, const float* __restrict__ b1,
                          const float* __restrict__ w2, const float* __restrict__ b2) {
    int node = blockIdx.x;
    int j = threadIdx.x;
    __shared__ float sx[FIN];
    __shared__ float sz[H];
    if (j < FIN) sx[j] = x[node * FIN + j];
    __syncthreads();
    float a = b1[j];
#pragma unroll
    for (int k = 0; k < FIN; k++) a += sx[k] * w1[k * H + j];
    sz[j] = silu_f(a);
    __syncthreads();
    float a2 = b2[j];
#pragma unroll 8
    for (int k = 0; k < H; k++) a2 += sz[k] * w2[k * H + j];
    g_h[node * H + j] = a2;
}

// ---------------- node projection: P = h @ [W1a | W1b] -------------------
__global__ void __launch_bounds__(256, 2)
k_nodeproj(const float* __restrict__ W1) {
    __shared__ float As[32 * SA];
    __shared__ float Bs[32 * SA];
    const int tile = blockIdx.x >> 1;
    const int half = blockIdx.x & 1;
    const int n0 = tile * 128;
    const int tid = threadIdx.x;
    const int tx = tid & 15, ty = tid >> 4;
    const int row0 = ty * 8, col0 = tx * 8;

    float acc[8][8];
#pragma unroll
    for (int r = 0; r < 8; r++)
#pragma unroll
        for (int c = 0; c < 8; c++) acc[r][c] = 0.0f;

    for (int t = 0; t < 4; t++) {
#pragma unroll
        for (int it = 0; it < 4; ++it) {
            int i = tid + it * 256;
            int idx = i >> 3, seg = i & 7;
            int node = n0 + idx;
            float4 v = make_float4(0.f, 0.f, 0.f, 0.f);
            if (node < NN) v = *(const float4*)&g_h[node * H + t * 32 + seg * 4];
            As[(seg * 4 + 0) * SA + idx] = v.x;
            As[(seg * 4 + 1) * SA + idx] = v.y;
            As[(seg * 4 + 2) * SA + idx] = v.z;
            As[(seg * 4 + 3) * SA + idx] = v.w;
        }
#pragma unroll
        for (int it = 0; it < 4; ++it) {
            int i = tid + it * 256;
            int rowk = i >> 5, c4 = i & 31;
            *(float4*)&Bs[rowk * SA + c4 * 4] =
                *(const float4*)&W1[(half * 128 + t * 32 + rowk) * H + c4 * 4];
        }
        __syncthreads();
#pragma unroll 4
        for (int kk = 0; kk < 32; ++kk) {
            float4 a0 = *(const float4*)&As[kk * SA + row0];
            float4 a1 = *(const float4*)&As[kk * SA + row0 + 4];
            float4 b0 = *(const float4*)&Bs[kk * SA + col0];
            float4 b1v = *(const float4*)&Bs[kk * SA + col0 + 4];
            float av[8] = {a0.x, a0.y, a0.z, a0.w, a1.x, a1.y, a1.z, a1.w};
            float bv[8] = {b0.x, b0.y, b0.z, b0.w, b1v.x, b1v.y, b1v.z, b1v.w};
#pragma unroll
            for (int r = 0; r < 8; r++)
#pragma unroll
                for (int c = 0; c < 8; c++) acc[r][c] += av[r] * bv[c];
        }
        __syncthreads();
    }

#pragma unroll
    for (int r = 0; r < 8; r++) {
        int node = n0 + row0 + r;
        if (node < NN) {
            float* dst = &g_P[(size_t)node * 256 + half * 128 + col0];
            *(float4*)dst = make_float4(acc[r][0], acc[r][1], acc[r][2], acc[r][3]);
            *(float4*)(dst + 4) = make_float4(acc[r][4], acc[r][5], acc[r][6], acc[r][7]);
        }
    }
}

// ---------------- fused edge layer (dst-sorted) --------------------------
__global__ void __launch_bounds__(256, 2)
k_edge2(const float* __restrict__ ea,
        const float* __restrict__ W1, const float* __restrict__ b1,
        const float* __restrict__ W2, const float* __restrict__ b2) {
    extern __shared__ float sm[];
    float* Zs = sm;                         // [128][SA]
    float* Bs = Zs + 128 * SA;              // [32][SA]
    int* sDst = (int*)(Bs + 32 * SA);       // [TE]
    int* sSrc = sDst + TE;                  // [TE]
    float* sEa = (float*)(sSrc + TE);       // [TE][3]
    float* sW1c = sEa + TE * 3;             // [3][128]
    float* sB1 = sW1c + 3 * H;              // [128]
    float* sB2 = sB1 + H;                   // [128]
    float* sInv = sB2 + H;                  // [TE]

    const int tid = threadIdx.x;
    const int e0 = blockIdx.x * TE;

    if (tid < TE) {
        int d = g_sdst[e0 + tid];
        sDst[tid] = d;
        sSrc[tid] = g_ssrc[e0 + tid];
        sInv[tid] = g_invdeg[d];
        int p = g_sperm[e0 + tid];
        sEa[tid * 3 + 0] = ea[p * 3 + 0];
        sEa[tid * 3 + 1] = ea[p * 3 + 1];
        sEa[tid * 3 + 2] = ea[p * 3 + 2];
    }
    // FIX (R2 bug): 3*H = 384 > blockDim 256 — must grid-stride this load.
    for (int i = tid; i < 3 * H; i += 256)
        sW1c[i] = W1[(256 + i / H) * H + (i % H)];
    if (tid < H) { sB1[tid] = b1[tid]; sB2[tid] = b2[tid]; }
    __syncthreads();

    // ---- phase 1: z1 elementwise (1 thread per edge-half)
    {
        int edge = tid >> 1;
        int ch = (tid & 1) * 64;
        const float* pa = &g_P[(size_t)sDst[edge] * 256 + ch];
        const float* pb = &g_P[(size_t)sSrc[edge] * 256 + 128 + ch];
        float ev0 = sEa[edge * 3 + 0], ev1 = sEa[edge * 3 + 1], ev2 = sEa[edge * 3 + 2];
#pragma unroll
        for (int q = 0; q < 16; q++) {
            float4 va = *(const float4*)&pa[q * 4];
            float4 vb = *(const float4*)&pb[q * 4];
            int c = ch + q * 4;
            float z0 = va.x + vb.x + ev0 * sW1c[c + 0] + ev1 * sW1c[128 + c + 0] + ev2 * sW1c[256 + c + 0] + sB1[c + 0];
            float z1 = va.y + vb.y + ev0 * sW1c[c + 1] + ev1 * sW1c[128 + c + 1] + ev2 * sW1c[256 + c + 1] + sB1[c + 1];
            float z2 = va.z + vb.z + ev0 * sW1c[c + 2] + ev1 * sW1c[128 + c + 2] + ev2 * sW1c[256 + c + 2] + sB1[c + 2];
            float z3 = va.w + vb.w + ev0 * sW1c[c + 3] + ev1 * sW1c[128 + c + 3] + ev2 * sW1c[256 + c + 3] + sB1[c + 3];
            *(float4*)&Zs[edge * SA + c] =
                make_float4(silu_f(z0), silu_f(z1), silu_f(z2), silu_f(z3));
        }
    }
    __syncthreads();

    // ---- phase 2: GEMM2 m = z1 @ W2
    const int tx = tid & 15, ty = tid >> 4;
    const int row0 = ty * 8, col0 = tx * 8;
    float acc[8][8];
#pragma unroll
    for (int r = 0; r < 8; r++)
#pragma unroll
        for (int c = 0; c < 8; c++) acc[r][c] = 0.0f;

    for (int t2 = 0; t2 < 4; t2++) {
#pragma unroll
        for (int it = 0; it < 4; ++it) {
            int i = tid + it * 256;
            int rowk = i >> 5, c4 = i & 31;
            *(float4*)&Bs[rowk * SA + c4 * 4] =
                *(const float4*)&W2[(t2 * 32 + rowk) * H + c4 * 4];
        }
        __syncthreads();
#pragma unroll 4
        for (int kk = 0; kk < 32; ++kk) {
            float4 b0 = *(const float4*)&Bs[kk * SA + col0];
            float4 b1v = *(const float4*)&Bs[kk * SA + col0 + 4];
            float bv[8] = {b0.x, b0.y, b0.z, b0.w, b1v.x, b1v.y, b1v.z, b1v.w};
            float av[8];
#pragma unroll
            for (int r = 0; r < 8; r++)
                av[r] = Zs[(row0 + r) * SA + t2 * 32 + kk];
#pragma unroll
            for (int r = 0; r < 8; r++)
#pragma unroll
                for (int c = 0; c < 8; c++) acc[r][c] += av[r] * bv[c];
        }
        __syncthreads();
    }

    // ---- phase 3: +b2, scale by invdeg, stash into Zs
#pragma unroll
    for (int r = 0; r < 8; r++) {
        float iv = sInv[row0 + r];
        float v[8];
#pragma unroll
        for (int c = 0; c < 8; c++) v[c] = (acc[r][c] + sB2[col0 + c]) * iv;
        *(float4*)&Zs[(row0 + r) * SA + col0] = make_float4(v[0], v[1], v[2], v[3]);
        *(float4*)&Zs[(row0 + r) * SA + col0 + 4] = make_float4(v[4], v[5], v[6], v[7]);
    }
    __syncthreads();

    // ---- phase 4: segmented reduction by dst (sorted), boundary atomics
    {
        int col = tid & 127;
        int half = tid >> 7;
        int rs = half * 64, re = rs + 64;
        float sum = 0.0f;
        int cur = sDst[rs];
        for (int r = rs; r < re; r++) {
            int d = sDst[r];
            if (d != cur) {
                atomicAdd(&g_agg[(size_t)cur * H + col], sum);
                sum = 0.0f;
                cur = d;
            }
            sum += Zs[r * SA + col];
        }
        atomicAdd(&g_agg[(size_t)cur * H + col], sum);
    }
}

// ---------------- residual update ----------------------------------------
__global__ void k_update() {
    int i = blockIdx.x * blockDim.x + threadIdx.x;
    if (i >= NN * H) return;
    float a = g_agg[i];
    g_agg[i] = 0.0f;
    g_h[i] += a;
}

// ---------------- decoder ------------------------------------------------
__global__ void k_decoder(const float* __restrict__ w1, const float* __restrict__ b1,
                          const float* __restrict__ w2, const float* __restrict__ b2,
                          const float* __restrict__ w3, const float* __restrict__ b3,
                          float* __restrict__ out) {
    int node = blockIdx.x;
    int j = threadIdx.x;
    __shared__ float sh[H];
    __shared__ float st1[H];
    __shared__ float st2[64];
    sh[j] = g_h[node * H + j];
    __syncthreads();
    float a = b1[j];
#pragma unroll 8
    for (int k = 0; k < H; k++) a += sh[k] * w1[k * H + j];
    st1[j] = silu_f(a);
    __syncthreads();
    if (j < 64) {
        float a2 = b2[j];
#pragma unroll 8
        for (int k = 0; k < H; k++) a2 += st1[k] * w2[k * 64 + j];
        st2[j] = silu_f(a2);
    }
    __syncthreads();
    if (j < FOUT) {
        float a3 = b3[j];
#pragma unroll
        for (int k = 0; k < 64; k++) a3 += st2[k] * w3[k * FOUT + j];
        out[node * FOUT + j] = a3;
    }
}

// ---------------- launch -------------------------------------------------
extern "C" void kernel_launch(void* const* d_in, const int* in_sizes, int n_in,
                              void* d_out, int out_size) {
    const float* x      = (const float*)d_in[0];
    const void*  ei     = d_in[1];
    const float* ea     = (const float*)d_in[2];
    const float* enc_w1 = (const float*)d_in[3];
    const float* enc_b1 = (const float*)d_in[4];
    const float* enc_w2 = (const float*)d_in[5];
    const float* enc_b2 = (const float*)d_in[6];
    const float* conv_w1 = (const float*)d_in[7];
    const float* conv_b1 = (const float*)d_in[8];
    const float* conv_w2 = (const float*)d_in[9];
    const float* conv_b2 = (const float*)d_in[10];
    const float* dec_w1 = (const float*)d_in[11];
    const float* dec_b1 = (const float*)d_in[12];
    const float* dec_w2 = (const float*)d_in[13];
    const float* dec_b2 = (const float*)d_in[14];
    const float* dec_w3 = (const float*)d_in[15];
    const float* dec_b3 = (const float*)d_in[16];

    const int SMEM = (128 * SA + 32 * SA) * (int)sizeof(float)
                   + 2 * TE * (int)sizeof(int)
                   + (TE * 3 + 3 * H + 2 * H + TE) * (int)sizeof(float);
    cudaFuncSetAttribute(k_edge2, cudaFuncAttributeMaxDynamicSharedMemorySize, SMEM);

    k_detect<<<1, 256>>>((const int*)ei);
    k_init<<<(NN * H + 255) / 256, 256>>>();
    k_convert<<<(EE + 255) / 256, 256>>>(ei);
    k_invdeg<<<(NN + 255) / 256, 256>>>();
    k_scan<<<1, 1024>>>();
    k_scatter<<<(EE + 255) / 256, 256>>>();
    k_encoder<<<NN, H>>>(x, enc_w1, enc_b1, enc_w2, enc_b2);

    const int nTiles = (NN + 127) / 128;  // 157
    for (int l = 0; l < NLAYERS; l++) {
        k_nodeproj<<<nTiles * 2, 256>>>(conv_w1 + (size_t)l * 259 * H);
        k_edge2<<<EE / TE, 256, SMEM>>>(ea,
                                        conv_w1 + (size_t)l * 259 * H,
                                        conv_b1 + (size_t)l * H,
                                        conv_w2 + (size_t)l * H * H,
                                        conv_b2 + (size_t)l * H);
        k_update<<<(NN * H + 255) / 256, 256>>>();
    }

    k_decoder<<<NN, H>>>(dec_w1, dec_b1, dec_w2, dec_b2, dec_w3, dec_b3, (float*)d_out);
}

// round 5
// speedup vs baseline: 2.4331x; 1.1996x over previous
#include <cuda_runtime.h>
#include <cuda_bf16.h>
#include <cstdint>

#define NN 20000
#define EE 320000
#define H 128
#define FIN 14
#define FOUT 9
#define NLAYERS 6
#define TE 128      // edges per CTA tile
#define SA 132      // smem row stride for fp32 GEMM kernels
#define ASTR 136    // bf16 operand row stride (elements) -> 272B, ldmatrix conflict-free
#define ZSTR 129

// ---------------- device scratch (no allocations allowed) ----------------
__device__ float g_h[NN * H];
__device__ float g_agg[NN * H];
__device__ float g_P[NN * 256];       // per-node projections [Pa | Pb]
__device__ float g_invdeg[NN];
__device__ int   g_src[EE];
__device__ int   g_dst[EE];
__device__ int   g_cnt[NN];
__device__ int   g_off[NN + 1];
__device__ int   g_ssrc[EE];          // dst-sorted
__device__ int   g_sdst[EE];
__device__ int   g_sperm[EE];
__device__ int   g_is64;
// W2^T hi/lo bf16 images, padded [n][ASTR] layout (matches smem B image)
__device__ __align__(16) __nv_bfloat16 g_W2h[NLAYERS * H * ASTR];
__device__ __align__(16) __nv_bfloat16 g_W2l[NLAYERS * H * ASTR];

__device__ __forceinline__ float silu_f(float x) {
    return x / (1.0f + __expf(-x));
}

__device__ __forceinline__ uint32_t smem_u32(const void* p) {
    uint32_t a;
    asm("{ .reg .u64 t; cvta.to.shared.u64 t, %1; cvt.u32.u64 %0, t; }" : "=r"(a) : "l"(p));
    return a;
}

__device__ __forceinline__ void ldsm4(uint32_t* r, uint32_t addr) {
    asm volatile("ldmatrix.sync.aligned.m8n8.x4.shared.b16 {%0,%1,%2,%3}, [%4];"
                 : "=r"(r[0]), "=r"(r[1]), "=r"(r[2]), "=r"(r[3]) : "r"(addr));
}

__device__ __forceinline__ void mma16816(float* d, const uint32_t* a,
                                         uint32_t b0, uint32_t b1) {
    asm volatile(
        "mma.sync.aligned.m16n8k16.row.col.f32.bf16.bf16.f32 "
        "{%0,%1,%2,%3}, {%4,%5,%6,%7}, {%8,%9}, {%0,%1,%2,%3};"
        : "+f"(d[0]), "+f"(d[1]), "+f"(d[2]), "+f"(d[3])
        : "r"(a[0]), "r"(a[1]), "r"(a[2]), "r"(a[3]), "r"(b0), "r"(b1));
}

// ---------------- preprocessing kernels ----------------------------------
__global__ void k_detect(const int* __restrict__ ei) {
    __shared__ int cnt;
    if (threadIdx.x == 0) cnt = 0;
    __syncthreads();
    int c = 0;
    for (int i = threadIdx.x; i < 1024; i += 256)
        if (ei[2 * i + 1] != 0) c++;
    if (c) atomicAdd(&cnt, c);
    __syncthreads();
    if (threadIdx.x == 0) g_is64 = (cnt == 0) ? 1 : 0;
}

__global__ void k_init() {
    int i = blockIdx.x * blockDim.x + threadIdx.x;
    if (i < NN * H) g_agg[i] = 0.0f;
    if (i < NN) g_cnt[i] = 0;
}

__global__ void k_convert(const void* __restrict__ ei) {
    int i = blockIdx.x * blockDim.x + threadIdx.x;
    if (i >= EE) return;
    int s, d;
    if (g_is64) {
        const long long* p = (const long long*)ei;
        s = (int)p[i];
        d = (int)p[EE + i];
    } else {
        const int* p = (const int*)ei;
        s = p[i];
        d = p[EE + i];
    }
    g_src[i] = s;
    g_dst[i] = d;
    atomicAdd(&g_cnt[d], 1);
}

__global__ void k_invdeg() {
    int i = blockIdx.x * blockDim.x + threadIdx.x;
    if (i < NN) g_invdeg[i] = 1.0f / fmaxf((float)g_cnt[i], 1.0f);
}

__global__ void k_scan() {
    __shared__ int buf[1024];
    __shared__ int carry;
    if (threadIdx.x == 0) carry = 0;
    __syncthreads();
    for (int base = 0; base < NN; base += 1024) {
        int i = base + threadIdx.x;
        int v = (i < NN) ? g_cnt[i] : 0;
        buf[threadIdx.x] = v;
        __syncthreads();
        for (int s = 1; s < 1024; s <<= 1) {
            int t = (threadIdx.x >= s) ? buf[threadIdx.x - s] : 0;
            __syncthreads();
            buf[threadIdx.x] += t;
            __syncthreads();
        }
        if (i < NN) {
            g_off[i] = carry + buf[threadIdx.x] - v;
            g_cnt[i] = 0;
        }
        __syncthreads();
        if (threadIdx.x == 1023) carry += buf[1023];
        __syncthreads();
    }
    if (threadIdx.x == 0) g_off[NN] = EE;
}

__global__ void k_scatter() {
    int e = blockIdx.x * blockDim.x + threadIdx.x;
    if (e >= EE) return;
    int d = g_dst[e];
    int pos = g_off[d] + atomicAdd(&g_cnt[d], 1);
    g_ssrc[pos] = g_src[e];
    g_sdst[pos] = d;
    g_sperm[pos] = e;
}

// W2^T -> padded [n][ASTR] bf16 hi/lo images (per layer, once per launch)
__global__ void k_prepw(const float* __restrict__ W2) {
    int l = blockIdx.y;
    int i = blockIdx.x * 256 + threadIdx.x;   // 0..16383
    int n = i >> 7, k = i & 127;
    float w = W2[(size_t)l * H * H + k * H + n];
    __nv_bfloat16 hi = __float2bfloat16_rn(w);
    float r = w - __bfloat162float(hi);
    __nv_bfloat16 lo = __float2bfloat16_rn(r);
    size_t off = (size_t)l * H * ASTR + n * ASTR + k;
    g_W2h[off] = hi;
    g_W2l[off] = lo;
}

// ---------------- encoder ------------------------------------------------
__global__ void k_encoder(const float* __restrict__ x,
                          const float* __restrict__ w1, const float* __restrict__ b1,
                          const float* __restrict__ w2, const float* __restrict__ b2) {
    int node = blockIdx.x;
    int j = threadIdx.x;
    __shared__ float sx[FIN];
    __shared__ float sz[H];
    if (j < FIN) sx[j] = x[node * FIN + j];
    __syncthreads();
    float a = b1[j];
#pragma unroll
    for (int k = 0; k < FIN; k++) a += sx[k] * w1[k * H + j];
    sz[j] = silu_f(a);
    __syncthreads();
    float a2 = b2[j];
#pragma unroll 8
    for (int k = 0; k < H; k++) a2 += sz[k] * w2[k * H + j];
    g_h[node * H + j] = a2;
}

// ---------------- node projection: P = h @ [W1a | W1b] (fp32 FFMA) ------
__global__ void __launch_bounds__(256, 2)
k_nodeproj(const float* __restrict__ W1) {
    __shared__ float As[32 * SA];
    __shared__ float Bs[32 * SA];
    const int tile = blockIdx.x >> 1;
    const int half = blockIdx.x & 1;
    const int n0 = tile * 128;
    const int tid = threadIdx.x;
    const int tx = tid & 15, ty = tid >> 4;
    const int row0 = ty * 8, col0 = tx * 8;

    float acc[8][8];
#pragma unroll
    for (int r = 0; r < 8; r++)
#pragma unroll
        for (int c = 0; c < 8; c++) acc[r][c] = 0.0f;

    for (int t = 0; t < 4; t++) {
#pragma unroll
        for (int it = 0; it < 4; ++it) {
            int i = tid + it * 256;
            int idx = i >> 3, seg = i & 7;
            int node = n0 + idx;
            float4 v = make_float4(0.f, 0.f, 0.f, 0.f);
            if (node < NN) v = *(const float4*)&g_h[node * H + t * 32 + seg * 4];
            As[(seg * 4 + 0) * SA + idx] = v.x;
            As[(seg * 4 + 1) * SA + idx] = v.y;
            As[(seg * 4 + 2) * SA + idx] = v.z;
            As[(seg * 4 + 3) * SA + idx] = v.w;
        }
#pragma unroll
        for (int it = 0; it < 4; ++it) {
            int i = tid + it * 256;
            int rowk = i >> 5, c4 = i & 31;
            *(float4*)&Bs[rowk * SA + c4 * 4] =
                *(const float4*)&W1[(half * 128 + t * 32 + rowk) * H + c4 * 4];
        }
        __syncthreads();
#pragma unroll 4
        for (int kk = 0; kk < 32; ++kk) {
            float4 a0 = *(const float4*)&As[kk * SA + row0];
            float4 a1 = *(const float4*)&As[kk * SA + row0 + 4];
            float4 b0 = *(const float4*)&Bs[kk * SA + col0];
            float4 b1v = *(const float4*)&Bs[kk * SA + col0 + 4];
            float av[8] = {a0.x, a0.y, a0.z, a0.w, a1.x, a1.y, a1.z, a1.w};
            float bv[8] = {b0.x, b0.y, b0.z, b0.w, b1v.x, b1v.y, b1v.z, b1v.w};
#pragma unroll
            for (int r = 0; r < 8; r++)
#pragma unroll
                for (int c = 0; c < 8; c++) acc[r][c] += av[r] * bv[c];
        }
        __syncthreads();
    }

#pragma unroll
    for (int r = 0; r < 8; r++) {
        int node = n0 + row0 + r;
        if (node < NN) {
            float* dst = &g_P[(size_t)node * 256 + half * 128 + col0];
            *(float4*)dst = make_float4(acc[r][0], acc[r][1], acc[r][2], acc[r][3]);
            *(float4*)(dst + 4) = make_float4(acc[r][4], acc[r][5], acc[r][6], acc[r][7]);
        }
    }
}

// ---------------- HMMA fused edge layer ----------------------------------
// SMEM byte offsets (dynamic smem base is 16B aligned):
#define OFF_AH 0
#define OFF_AL 34816
#define OFF_BH 69632
#define OFF_BL 104448
#define OFF_MISC 139264
#define OFF_DST  (OFF_MISC + 0)
#define OFF_SRC  (OFF_MISC + 512)
#define OFF_INV  (OFF_MISC + 1024)
#define OFF_EA   (OFF_MISC + 1536)
#define OFF_W1C  (OFF_MISC + 3072)
#define OFF_B1   (OFF_MISC + 4608)
#define OFF_B2   (OFF_MISC + 5120)
#define SMEM_EDGE (OFF_MISC + 5632)

__global__ void __launch_bounds__(512, 1)
k_edge4(const float* __restrict__ ea, int layer,
        const float* __restrict__ W1, const float* __restrict__ b1,
        const float* __restrict__ b2) {
    extern __shared__ char smb[];
    const uint32_t sb = smem_u32(smb);

    int*   sDst = (int*)(smb + OFF_DST);
    int*   sSrc = (int*)(smb + OFF_SRC);
    float* sInv = (float*)(smb + OFF_INV);
    float* sEa  = (float*)(smb + OFF_EA);
    float* sW1c = (float*)(smb + OFF_W1C);
    float* sB1  = (float*)(smb + OFF_B1);
    float* sB2  = (float*)(smb + OFF_B2);

    const int tid = threadIdx.x;
    const int lid = tid & 31;
    const int wid = tid >> 5;
    const int e0 = blockIdx.x * TE;

    // ---- misc loads
    if (tid < TE) {
        int d = g_sdst[e0 + tid];
        sDst[tid] = d;
        sSrc[tid] = g_ssrc[e0 + tid];
        sInv[tid] = g_invdeg[d];
        int p = g_sperm[e0 + tid];
        sEa[tid * 3 + 0] = ea[p * 3 + 0];
        sEa[tid * 3 + 1] = ea[p * 3 + 1];
        sEa[tid * 3 + 2] = ea[p * 3 + 2];
        sB2[tid] = b2[tid];
    }
    {
        int t = tid - 128;
        if (t >= 0 && t < 384) sW1c[t] = W1[(256 + t / H) * H + (t % H)];
    }
    if (tid >= 384) sB1[tid - 384] = b1[tid - 384];

    // ---- B copy: W2^T hi/lo padded images (straight uint4 copy)
    {
        const uint4* srcH = (const uint4*)(g_W2h + (size_t)layer * H * ASTR);
        const uint4* srcL = (const uint4*)(g_W2l + (size_t)layer * H * ASTR);
        uint4* dstH = (uint4*)(smb + OFF_BH);
        uint4* dstL = (uint4*)(smb + OFF_BL);
        for (int i = tid; i < H * ASTR / 8; i += 512) {   // 2176 uint4
            dstH[i] = srcH[i];
            dstL[i] = srcL[i];
        }
    }
    __syncthreads();

    // ---- z1 phase: silu(Pa[dst]+Pb[src]+ea*W1c+b1), split bf16 hi/lo into A
    {
        int edge = tid >> 2;
        int ch0 = (tid & 3) * 32;
        const float* pa = &g_P[(size_t)sDst[edge] * 256 + ch0];
        const float* pb = &g_P[(size_t)sSrc[edge] * 256 + 128 + ch0];
        float ev0 = sEa[edge * 3 + 0], ev1 = sEa[edge * 3 + 1], ev2 = sEa[edge * 3 + 2];
#pragma unroll
        for (int q = 0; q < 8; q++) {
            int c = ch0 + q * 4;
            float4 va = *(const float4*)&pa[q * 4];
            float4 vb = *(const float4*)&pb[q * 4];
            float z0 = silu_f(va.x + vb.x + ev0 * sW1c[c + 0] + ev1 * sW1c[128 + c + 0] + ev2 * sW1c[256 + c + 0] + sB1[c + 0]);
            float z1 = silu_f(va.y + vb.y + ev0 * sW1c[c + 1] + ev1 * sW1c[128 + c + 1] + ev2 * sW1c[256 + c + 1] + sB1[c + 1]);
            float z2 = silu_f(va.z + vb.z + ev0 * sW1c[c + 2] + ev1 * sW1c[128 + c + 2] + ev2 * sW1c[256 + c + 2] + sB1[c + 2]);
            float z3 = silu_f(va.w + vb.w + ev0 * sW1c[c + 3] + ev1 * sW1c[128 + c + 3] + ev2 * sW1c[256 + c + 3] + sB1[c + 3]);
            __nv_bfloat16 h0 = __float2bfloat16_rn(z0);
            __nv_bfloat16 h1 = __float2bfloat16_rn(z1);
            __nv_bfloat16 h2 = __float2bfloat16_rn(z2);
            __nv_bfloat16 h3 = __float2bfloat16_rn(z3);
            __nv_bfloat16 l0 = __float2bfloat16_rn(z0 - __bfloat162float(h0));
            __nv_bfloat16 l1 = __float2bfloat16_rn(z1 - __bfloat162float(h1));
            __nv_bfloat16 l2 = __float2bfloat16_rn(z2 - __bfloat162float(h2));
            __nv_bfloat16 l3 = __float2bfloat16_rn(z3 - __bfloat162float(h3));
            __nv_bfloat162 ph0; ph0.x = h0; ph0.y = h1;
            __nv_bfloat162 ph1; ph1.x = h2; ph1.y = h3;
            __nv_bfloat162 pl0; pl0.x = l0; pl0.y = l1;
            __nv_bfloat162 pl1; pl1.x = l2; pl1.y = l3;
            uint2 uh; uh.x = *(uint32_t*)&ph0; uh.y = *(uint32_t*)&ph1;
            uint2 ul; ul.x = *(uint32_t*)&pl0; ul.y = *(uint32_t*)&pl1;
            uint32_t off = (uint32_t)edge * (ASTR * 2) + (uint32_t)c * 2;  // bytes
            *(uint2*)(smb + OFF_AH + off) = uh;
            *(uint2*)(smb + OFF_AL + off) = ul;
        }
    }
    __syncthreads();

    // ---- HMMA: 4x4 warp grid, each warp 32(edges) x 32(cols)
    const int row0 = (wid >> 2) * 32;
    const int col0 = (wid & 3) * 32;
    float d[2][4][4];
#pragma unroll
    for (int mt = 0; mt < 2; mt++)
#pragma unroll
        for (int nt = 0; nt < 4; nt++)
#pragma unroll
            for (int q = 0; q < 4; q++) d[mt][nt][q] = 0.0f;

    // precomputed intra-warp fragment coordinates
    const int a_r = lid & 15, a_c8 = (lid >> 4) * 8;
    const int b_g = lid >> 3;
    const int b_n = (b_g >> 1) * 8 + (lid & 7);
    const int b_c8 = (b_g & 1) * 8;

#pragma unroll 2
    for (int ks = 0; ks < 8; ks++) {
        const int k0 = ks * 16;
        uint32_t ah[2][4], al[2][4], bh[2][4], bl[2][4];
#pragma unroll
        for (int mt = 0; mt < 2; mt++) {
            uint32_t addr = sb + OFF_AH
                          + (uint32_t)(row0 + mt * 16 + a_r) * (ASTR * 2)
                          + (uint32_t)(k0 + a_c8) * 2;
            ldsm4(ah[mt], addr);
            ldsm4(al[mt], addr + (OFF_AL - OFF_AH));
        }
#pragma unroll
        for (int bt = 0; bt < 2; bt++) {
            uint32_t addr = sb + OFF_BH
                          + (uint32_t)(col0 + bt * 16 + b_n) * (ASTR * 2)
                          + (uint32_t)(k0 + b_c8) * 2;
            ldsm4(bh[bt], addr);
            ldsm4(bl[bt], addr + (OFF_BL - OFF_BH));
        }
#pragma unroll
        for (int mt = 0; mt < 2; mt++)
#pragma unroll
            for (int nt = 0; nt < 4; nt++) {
                uint32_t bh0 = bh[nt >> 1][(nt & 1) * 2], bh1 = bh[nt >> 1][(nt & 1) * 2 + 1];
                uint32_t bl0 = bl[nt >> 1][(nt & 1) * 2], bl1 = bl[nt >> 1][(nt & 1) * 2 + 1];
                mma16816(d[mt][nt], ah[mt], bh0, bh1);
                mma16816(d[mt][nt], ah[mt], bl0, bl1);
                mma16816(d[mt][nt], al[mt], bh0, bh1);
            }
    }
    __syncthreads();   // all warps done reading A/B; safe to overlay Zs on A

    // ---- epilogue: +b2, *invdeg, stage fragments to Zs
    float* Zs = (float*)(smb + OFF_AH);
    {
        const int fr = lid >> 2, fc = (lid & 3) * 2;
#pragma unroll
        for (int mt = 0; mt < 2; mt++) {
            int r = row0 + mt * 16 + fr;
            float iv0 = sInv[r], iv8 = sInv[r + 8];
#pragma unroll
            for (int nt = 0; nt < 4; nt++) {
                int cc = col0 + nt * 8 + fc;
                float bb0 = sB2[cc], bb1 = sB2[cc + 1];
                Zs[r * ZSTR + cc]           = (d[mt][nt][0] + bb0) * iv0;
                Zs[r * ZSTR + cc + 1]       = (d[mt][nt][1] + bb1) * iv0;
                Zs[(r + 8) * ZSTR + cc]     = (d[mt][nt][2] + bb0) * iv8;
                Zs[(r + 8) * ZSTR + cc + 1] = (d[mt][nt][3] + bb1) * iv8;
            }
        }
    }
    __syncthreads();

    // ---- segmented reduction by dst (sorted), boundary atomics
    {
        int col = tid & 127;
        int q = tid >> 7;            // 4 segments of 32 rows
        int rs = q * 32, re = rs + 32;
        float sum = 0.0f;
        int cur = sDst[rs];
        for (int r = rs; r < re; r++) {
            int dn = sDst[r];
            if (dn != cur) {
                atomicAdd(&g_agg[(size_t)cur * H + col], sum);
                sum = 0.0f;
                cur = dn;
            }
            sum += Zs[r * ZSTR + col];
        }
        atomicAdd(&g_agg[(size_t)cur * H + col], sum);
    }
}

// ---------------- residual update ----------------------------------------
__global__ void k_update() {
    int i = blockIdx.x * blockDim.x + threadIdx.x;
    if (i >= NN * H) return;
    float a = g_agg[i];
    g_agg[i] = 0.0f;
    g_h[i] += a;
}

// ---------------- decoder ------------------------------------------------
__global__ void k_decoder(const float* __restrict__ w1, const float* __restrict__ b1,
                          const float* __restrict__ w2, const float* __restrict__ b2,
                          const float* __restrict__ w3, const float* __restrict__ b3,
                          float* __restrict__ out) {
    int node = blockIdx.x;
    int j = threadIdx.x;
    __shared__ float sh[H];
    __shared__ float st1[H];
    __shared__ float st2[64];
    sh[j] = g_h[node * H + j];
    __syncthreads();
    float a = b1[j];
#pragma unroll 8
    for (int k = 0; k < H; k++) a += sh[k] * w1[k * H + j];
    st1[j] = silu_f(a);
    __syncthreads();
    if (j < 64) {
        float a2 = b2[j];
#pragma unroll 8
        for (int k = 0; k < H; k++) a2 += st1[k] * w2[k * 64 + j];
        st2[j] = silu_f(a2);
    }
    __syncthreads();
    if (j < FOUT) {
        float a3 = b3[j];
#pragma unroll
        for (int k = 0; k < 64; k++) a3 += st2[k] * w3[k * FOUT + j];
        out[node * FOUT + j] = a3;
    }
}

// ---------------- launch -------------------------------------------------
extern "C" void kernel_launch(void* const* d_in, const int* in_sizes, int n_in,
                              void* d_out, int out_size) {
    const float* x      = (const float*)d_in[0];
    const void*  ei     = d_in[1];
    const float* ea     = (const float*)d_in[2];
    const float* enc_w1 = (const float*)d_in[3];
    const float* enc_b1 = (const float*)d_in[4];
    const float* enc_w2 = (const float*)d_in[5];
    const float* enc_b2 = (const float*)d_in[6];
    const float* conv_w1 = (const float*)d_in[7];
    const float* conv_b1 = (const float*)d_in[8];
    const float* conv_w2 = (const float*)d_in[9];
    const float* conv_b2 = (const float*)d_in[10];
    const float* dec_w1 = (const float*)d_in[11];
    const float* dec_b1 = (const float*)d_in[12];
    const float* dec_w2 = (const float*)d_in[13];
    const float* dec_b2 = (const float*)d_in[14];
    const float* dec_w3 = (const float*)d_in[15];
    const float* dec_b3 = (const float*)d_in[16];

    cudaFuncSetAttribute(k_edge4, cudaFuncAttributeMaxDynamicSharedMemorySize, SMEM_EDGE);

    k_detect<<<1, 256>>>((const int*)ei);
    k_init<<<(NN * H + 255) / 256, 256>>>();
    k_convert<<<(EE + 255) / 256, 256>>>(ei);
    k_invdeg<<<(NN + 255) / 256, 256>>>();
    k_scan<<<1, 1024>>>();
    k_scatter<<<(EE + 255) / 256, 256>>>();
    {
        dim3 g(64, NLAYERS);
        k_prepw<<<g, 256>>>(conv_w2);
    }
    k_encoder<<<NN, H>>>(x, enc_w1, enc_b1, enc_w2, enc_b2);

    const int nTiles = (NN + 127) / 128;
    for (int l = 0; l < NLAYERS; l++) {
        k_nodeproj<<<nTiles * 2, 256>>>(conv_w1 + (size_t)l * 259 * H);
        k_edge4<<<EE / TE, 512, SMEM_EDGE>>>(ea, l,
                                             conv_w1 + (size_t)l * 259 * H,
                                             conv_b1 + (size_t)l * H,
                                             conv_b2 + (size_t)l * H);
        k_update<<<(NN * H + 255) / 256, 256>>>();
    }

    k_decoder<<<NN, H>>>(dec_w1, dec_b1, dec_w2, dec_b2, dec_w3, dec_b3, (float*)d_out);
}

// round 6
// speedup vs baseline: 3.1802x; 1.3070x over previous
#include <cuda_runtime.h>
#include <cuda_bf16.h>
#include <cstdint>

#define NN 20000
#define EE 320000
#define H 128
#define FIN 14
#define FOUT 9
#define NLAYERS 6
#define TE 128
#define NTILES (EE / TE)          // 2500
#define GRID_EDGE 148
#define SA 132                    // fp32 GEMM smem stride
#define ASTR 136                  // bf16 operand row stride (elems), 272B
#define ZSTR 129

// ---------------- device scratch ----------------
__device__ float g_h[NN * H];
__device__ float g_agg[NN * H];
__device__ float g_P[NN * 256];
__device__ float g_invdeg[NN];
__device__ int   g_src[EE];
__device__ int   g_dst[EE];
__device__ int   g_cnt[NN];
__device__ int   g_off[NN + 1];
__device__ int   g_ssrc[EE];
__device__ int   g_sdst[EE];
__device__ int   g_sperm[EE];
__device__ int   g_is64;
__device__ __align__(16) __nv_bfloat16 g_W2h[NLAYERS * H * ASTR];
__device__ __align__(16) __nv_bfloat16 g_W2l[NLAYERS * H * ASTR];

__device__ __forceinline__ float silu_f(float x) {
    return x / (1.0f + __expf(-x));
}

__device__ __forceinline__ uint32_t smem_u32(const void* p) {
    uint32_t a;
    asm("{ .reg .u64 t; cvta.to.shared.u64 t, %1; cvt.u32.u64 %0, t; }" : "=r"(a) : "l"(p));
    return a;
}

__device__ __forceinline__ void ldsm4(uint32_t* r, uint32_t addr) {
    asm volatile("ldmatrix.sync.aligned.m8n8.x4.shared.b16 {%0,%1,%2,%3}, [%4];"
                 : "=r"(r[0]), "=r"(r[1]), "=r"(r[2]), "=r"(r[3]) : "r"(addr));
}

__device__ __forceinline__ void mma16816(float* d, const uint32_t* a,
                                         uint32_t b0, uint32_t b1) {
    asm volatile(
        "mma.sync.aligned.m16n8k16.row.col.f32.bf16.bf16.f32 "
        "{%0,%1,%2,%3}, {%4,%5,%6,%7}, {%8,%9}, {%0,%1,%2,%3};"
        : "+f"(d[0]), "+f"(d[1]), "+f"(d[2]), "+f"(d[3])
        : "r"(a[0]), "r"(a[1]), "r"(a[2]), "r"(a[3]), "r"(b0), "r"(b1));
}

// ---------------- preprocessing ----------------
__global__ void k_detect(const int* __restrict__ ei) {
    __shared__ int cnt;
    if (threadIdx.x == 0) cnt = 0;
    __syncthreads();
    int c = 0;
    for (int i = threadIdx.x; i < 1024; i += 256)
        if (ei[2 * i + 1] != 0) c++;
    if (c) atomicAdd(&cnt, c);
    __syncthreads();
    if (threadIdx.x == 0) g_is64 = (cnt == 0) ? 1 : 0;
}

__global__ void k_init() {
    int i = blockIdx.x * blockDim.x + threadIdx.x;
    if (i < NN * H) g_agg[i] = 0.0f;
    if (i < NN) g_cnt[i] = 0;
}

__global__ void k_convert(const void* __restrict__ ei) {
    int i = blockIdx.x * blockDim.x + threadIdx.x;
    if (i >= EE) return;
    int s, d;
    if (g_is64) {
        const long long* p = (const long long*)ei;
        s = (int)p[i];
        d = (int)p[EE + i];
    } else {
        const int* p = (const int*)ei;
        s = p[i];
        d = p[EE + i];
    }
    g_src[i] = s;
    g_dst[i] = d;
    atomicAdd(&g_cnt[d], 1);
}

__global__ void k_invdeg() {
    int i = blockIdx.x * blockDim.x + threadIdx.x;
    if (i < NN) g_invdeg[i] = 1.0f / fmaxf((float)g_cnt[i], 1.0f);
}

__global__ void k_scan() {
    __shared__ int buf[1024];
    __shared__ int carry;
    if (threadIdx.x == 0) carry = 0;
    __syncthreads();
    for (int base = 0; base < NN; base += 1024) {
        int i = base + threadIdx.x;
        int v = (i < NN) ? g_cnt[i] : 0;
        buf[threadIdx.x] = v;
        __syncthreads();
        for (int s = 1; s < 1024; s <<= 1) {
            int t = (threadIdx.x >= s) ? buf[threadIdx.x - s] : 0;
            __syncthreads();
            buf[threadIdx.x] += t;
            __syncthreads();
        }
        if (i < NN) {
            g_off[i] = carry + buf[threadIdx.x] - v;
            g_cnt[i] = 0;
        }
        __syncthreads();
        if (threadIdx.x == 1023) carry += buf[1023];
        __syncthreads();
    }
    if (threadIdx.x == 0) g_off[NN] = EE;
}

__global__ void k_scatter() {
    int e = blockIdx.x * blockDim.x + threadIdx.x;
    if (e >= EE) return;
    int d = g_dst[e];
    int pos = g_off[d] + atomicAdd(&g_cnt[d], 1);
    g_ssrc[pos] = g_src[e];
    g_sdst[pos] = d;
    g_sperm[pos] = e;
}

__global__ void k_prepw(const float* __restrict__ W2) {
    int l = blockIdx.y;
    int i = blockIdx.x * 256 + threadIdx.x;
    int n = i >> 7, k = i & 127;
    float w = W2[(size_t)l * H * H + k * H + n];
    __nv_bfloat16 hi = __float2bfloat16_rn(w);
    float r = w - __bfloat162float(hi);
    __nv_bfloat16 lo = __float2bfloat16_rn(r);
    size_t off = (size_t)l * H * ASTR + n * ASTR + k;
    g_W2h[off] = hi;
    g_W2l[off] = lo;
}

// ---------------- encoder ----------------
__global__ void k_encoder(const float* __restrict__ x,
                          const float* __restrict__ w1, const float* __restrict__ b1,
                          const float* __restrict__ w2, const float* __restrict__ b2) {
    int node = blockIdx.x;
    int j = threadIdx.x;
    __shared__ float sx[FIN];
    __shared__ float sz[H];
    if (j < FIN) sx[j] = x[node * FIN + j];
    __syncthreads();
    float a = b1[j];
#pragma unroll
    for (int k = 0; k < FIN; k++) a += sx[k] * w1[k * H + j];
    sz[j] = silu_f(a);
    __syncthreads();
    float a2 = b2[j];
#pragma unroll 8
    for (int k = 0; k < H; k++) a2 += sz[k] * w2[k * H + j];
    g_h[node * H + j] = a2;
}

// ---------------- node projection (fp32 FFMA) ----------------
__global__ void __launch_bounds__(256, 2)
k_nodeproj(const float* __restrict__ W1) {
    __shared__ float As[32 * SA];
    __shared__ float Bs[32 * SA];
    const int tile = blockIdx.x >> 1;
    const int half = blockIdx.x & 1;
    const int n0 = tile * 128;
    const int tid = threadIdx.x;
    const int tx = tid & 15, ty = tid >> 4;
    const int row0 = ty * 8, col0 = tx * 8;

    float acc[8][8];
#pragma unroll
    for (int r = 0; r < 8; r++)
#pragma unroll
        for (int c = 0; c < 8; c++) acc[r][c] = 0.0f;

    for (int t = 0; t < 4; t++) {
#pragma unroll
        for (int it = 0; it < 4; ++it) {
            int i = tid + it * 256;
            int idx = i >> 3, seg = i & 7;
            int node = n0 + idx;
            float4 v = make_float4(0.f, 0.f, 0.f, 0.f);
            if (node < NN) v = *(const float4*)&g_h[node * H + t * 32 + seg * 4];
            As[(seg * 4 + 0) * SA + idx] = v.x;
            As[(seg * 4 + 1) * SA + idx] = v.y;
            As[(seg * 4 + 2) * SA + idx] = v.z;
            As[(seg * 4 + 3) * SA + idx] = v.w;
        }
#pragma unroll
        for (int it = 0; it < 4; ++it) {
            int i = tid + it * 256;
            int rowk = i >> 5, c4 = i & 31;
            *(float4*)&Bs[rowk * SA + c4 * 4] =
                *(const float4*)&W1[(half * 128 + t * 32 + rowk) * H + c4 * 4];
        }
        __syncthreads();
#pragma unroll 4
        for (int kk = 0; kk < 32; ++kk) {
            float4 a0 = *(const float4*)&As[kk * SA + row0];
            float4 a1 = *(const float4*)&As[kk * SA + row0 + 4];
            float4 b0 = *(const float4*)&Bs[kk * SA + col0];
            float4 b1v = *(const float4*)&Bs[kk * SA + col0 + 4];
            float av[8] = {a0.x, a0.y, a0.z, a0.w, a1.x, a1.y, a1.z, a1.w};
            float bv[8] = {b0.x, b0.y, b0.z, b0.w, b1v.x, b1v.y, b1v.z, b1v.w};
#pragma unroll
            for (int r = 0; r < 8; r++)
#pragma unroll
                for (int c = 0; c < 8; c++) acc[r][c] += av[r] * bv[c];
        }
        __syncthreads();
    }

#pragma unroll
    for (int r = 0; r < 8; r++) {
        int node = n0 + row0 + r;
        if (node < NN) {
            float* dst = &g_P[(size_t)node * 256 + half * 128 + col0];
            *(float4*)dst = make_float4(acc[r][0], acc[r][1], acc[r][2], acc[r][3]);
            *(float4*)(dst + 4) = make_float4(acc[r][4], acc[r][5], acc[r][6], acc[r][7]);
        }
    }
}

// ---------------- persistent warp-specialized edge layer ------------------
// SMEM byte offsets:
#define OFF_A0H 0
#define OFF_A0L 34816
#define OFF_A1H 69632
#define OFF_A1L 104448
#define OFF_BH  139264
#define OFF_BL  174080
#define OFF_SDST 208896          // int [2][128]
#define OFF_SINV 209920          // float [2][128]
#define OFF_W1C  210944          // float [384]
#define OFF_B1   212480          // float [128]
#define OFF_B2   212992          // float [128]
#define SMEM_EDGE 213504

// producer fill: 256 threads, 2 per edge (64 cols each)
__device__ __forceinline__ void fill_tile(char* smb, int buf, int tileIdx, int ptid,
                                          const float* __restrict__ ea,
                                          const float* sW1c, const float* sB1) {
    const int e0 = tileIdx * TE;
    const int edge = ptid >> 1;
    const int ch0 = (ptid & 1) * 64;
    int dn = g_sdst[e0 + edge];
    int sn = g_ssrc[e0 + edge];
    if ((ptid & 1) == 0) {
        ((int*)(smb + OFF_SDST))[buf * 128 + edge] = dn;
        ((float*)(smb + OFF_SINV))[buf * 128 + edge] = g_invdeg[dn];
    }
    int p = g_sperm[e0 + edge];
    float ev0 = ea[p * 3 + 0], ev1 = ea[p * 3 + 1], ev2 = ea[p * 3 + 2];
    const float* pa = &g_P[(size_t)dn * 256 + ch0];
    const float* pb = &g_P[(size_t)sn * 256 + 128 + ch0];
    const uint32_t abase = buf ? OFF_A1H : OFF_A0H;
#pragma unroll
    for (int q = 0; q < 16; q++) {
        int c = ch0 + q * 4;
        float4 va = *(const float4*)&pa[q * 4];
        float4 vb = *(const float4*)&pb[q * 4];
        float z0 = silu_f(va.x + vb.x + ev0 * sW1c[c + 0] + ev1 * sW1c[128 + c + 0] + ev2 * sW1c[256 + c + 0] + sB1[c + 0]);
        float z1 = silu_f(va.y + vb.y + ev0 * sW1c[c + 1] + ev1 * sW1c[128 + c + 1] + ev2 * sW1c[256 + c + 1] + sB1[c + 1]);
        float z2 = silu_f(va.z + vb.z + ev0 * sW1c[c + 2] + ev1 * sW1c[128 + c + 2] + ev2 * sW1c[256 + c + 2] + sB1[c + 2]);
        float z3 = silu_f(va.w + vb.w + ev0 * sW1c[c + 3] + ev1 * sW1c[128 + c + 3] + ev2 * sW1c[256 + c + 3] + sB1[c + 3]);
        __nv_bfloat16 h0 = __float2bfloat16_rn(z0);
        __nv_bfloat16 h1 = __float2bfloat16_rn(z1);
        __nv_bfloat16 h2 = __float2bfloat16_rn(z2);
        __nv_bfloat16 h3 = __float2bfloat16_rn(z3);
        __nv_bfloat16 l0 = __float2bfloat16_rn(z0 - __bfloat162float(h0));
        __nv_bfloat16 l1 = __float2bfloat16_rn(z1 - __bfloat162float(h1));
        __nv_bfloat16 l2 = __float2bfloat16_rn(z2 - __bfloat162float(h2));
        __nv_bfloat16 l3 = __float2bfloat16_rn(z3 - __bfloat162float(h3));
        __nv_bfloat162 ph0; ph0.x = h0; ph0.y = h1;
        __nv_bfloat162 ph1; ph1.x = h2; ph1.y = h3;
        __nv_bfloat162 pl0; pl0.x = l0; pl0.y = l1;
        __nv_bfloat162 pl1; pl1.x = l2; pl1.y = l3;
        uint2 uh; uh.x = *(uint32_t*)&ph0; uh.y = *(uint32_t*)&ph1;
        uint2 ul; ul.x = *(uint32_t*)&pl0; ul.y = *(uint32_t*)&pl1;
        uint32_t off = (uint32_t)edge * (ASTR * 2) + (uint32_t)c * 2;
        *(uint2*)(smb + abase + off) = uh;
        *(uint2*)(smb + abase + 34816 + off) = ul;
    }
}

__global__ void __launch_bounds__(512, 1)
k_edge5(const float* __restrict__ ea, int layer,
        const float* __restrict__ W1, const float* __restrict__ b1,
        const float* __restrict__ b2) {
    extern __shared__ char smb[];
    const uint32_t sb = smem_u32(smb);
    const int tid = threadIdx.x;
    const int lid = tid & 31;
    const int wid = tid >> 5;
    const bool producer = (wid < 8);
    const int bid = blockIdx.x;

    float* sW1c = (float*)(smb + OFF_W1C);
    float* sB1  = (float*)(smb + OFF_B1);
    float* sB2  = (float*)(smb + OFF_B2);

    // ---- prologue: B (once per CTA), W1c, biases
    {
        const uint4* srcH = (const uint4*)(g_W2h + (size_t)layer * H * ASTR);
        const uint4* srcL = (const uint4*)(g_W2l + (size_t)layer * H * ASTR);
        uint4* dstH = (uint4*)(smb + OFF_BH);
        uint4* dstL = (uint4*)(smb + OFF_BL);
        for (int i = tid; i < H * ASTR / 8; i += 512) {
            dstH[i] = srcH[i];
            dstL[i] = srcL[i];
        }
    }
    if (tid < 384) sW1c[tid] = W1[(256 + tid / H) * H + (tid % H)];
    else if (tid < 512) sB1[tid - 384] = b1[tid - 384];
    if (tid < 128) sB2[tid] = b2[tid];
    __syncthreads();

    const int n = (NTILES - bid + GRID_EDGE - 1) / GRID_EDGE;
    if (producer) fill_tile(smb, 0, bid, tid, ea, sW1c, sB1);

    // consumer constants
    const int cwid = wid - 8;
    const int row0 = (cwid >> 1) * 32;
    const int col0 = (cwid & 1) * 64;
    const int a_r = lid & 15, a_c8 = (lid >> 4) * 8;
    const int b_g = lid >> 3;
    const int b_n = (b_g >> 1) * 8 + (lid & 7);
    const int b_c8 = (b_g & 1) * 8;

    for (int k = 0; k < n; k++) {
        const int cur = k & 1;
        asm volatile("bar.sync 1, 512;" ::: "memory");
        if (producer) {
            if (k + 1 < n)
                fill_tile(smb, cur ^ 1, bid + (k + 1) * GRID_EDGE, tid, ea, sW1c, sB1);
        } else {
            const uint32_t abase = cur ? OFF_A1H : OFF_A0H;
            float d[2][8][4];
#pragma unroll
            for (int mt = 0; mt < 2; mt++)
#pragma unroll
                for (int nt = 0; nt < 8; nt++)
#pragma unroll
                    for (int q = 0; q < 4; q++) d[mt][nt][q] = 0.0f;

#pragma unroll 1
            for (int ks = 0; ks < 8; ks++) {
                const int k0 = ks * 16;
                uint32_t ah[2][4], al[2][4];
#pragma unroll
                for (int mt = 0; mt < 2; mt++) {
                    uint32_t addr = sb + abase
                                  + (uint32_t)(row0 + mt * 16 + a_r) * (ASTR * 2)
                                  + (uint32_t)(k0 + a_c8) * 2;
                    ldsm4(ah[mt], addr);
                    ldsm4(al[mt], addr + 34816);
                }
#pragma unroll
                for (int bt = 0; bt < 4; bt++) {
                    uint32_t bh[4], bl[4];
                    uint32_t addr = sb + OFF_BH
                                  + (uint32_t)(col0 + bt * 16 + b_n) * (ASTR * 2)
                                  + (uint32_t)(k0 + b_c8) * 2;
                    ldsm4(bh, addr);
                    ldsm4(bl, addr + (OFF_BL - OFF_BH));
                    const int nt0 = bt * 2, nt1 = bt * 2 + 1;
#pragma unroll
                    for (int mt = 0; mt < 2; mt++) {
                        mma16816(d[mt][nt0], ah[mt], bh[0], bh[1]);
                        mma16816(d[mt][nt1], ah[mt], bh[2], bh[3]);
                        mma16816(d[mt][nt0], ah[mt], bl[0], bl[1]);
                        mma16816(d[mt][nt1], ah[mt], bl[2], bl[3]);
                        mma16816(d[mt][nt0], al[mt], bh[0], bh[1]);
                        mma16816(d[mt][nt1], al[mt], bh[2], bh[3]);
                    }
                }
            }
            asm volatile("bar.sync 2, 256;" ::: "memory");   // A[cur] fully read

            // epilogue: +b2, *invdeg -> Zs (overlay A[cur])
            float* Zs = (float*)(smb + abase);
            const float* sInvC = (const float*)(smb + OFF_SINV) + cur * 128;
            const int fr = lid >> 2, fc = (lid & 3) * 2;
#pragma unroll
            for (int mt = 0; mt < 2; mt++) {
                int r = row0 + mt * 16 + fr;
                float iv0 = sInvC[r], iv8 = sInvC[r + 8];
#pragma unroll
                for (int nt = 0; nt < 8; nt++) {
                    int cc = col0 + nt * 8 + fc;
                    float bb0 = sB2[cc], bb1 = sB2[cc + 1];
                    Zs[r * ZSTR + cc]           = (d[mt][nt][0] + bb0) * iv0;
                    Zs[r * ZSTR + cc + 1]       = (d[mt][nt][1] + bb1) * iv0;
                    Zs[(r + 8) * ZSTR + cc]     = (d[mt][nt][2] + bb0) * iv8;
                    Zs[(r + 8) * ZSTR + cc + 1] = (d[mt][nt][3] + bb1) * iv8;
                }
            }
            asm volatile("bar.sync 2, 256;" ::: "memory");

            // segmented reduction (dst-sorted): 256 threads, 128 cols x 2 segs
            {
                const int ctid = tid - 256;
                const int col = ctid & 127;
                const int seg = ctid >> 7;
                const int rs = seg * 64, re = rs + 64;
                const int* sDstC = (const int*)(smb + OFF_SDST) + cur * 128;
                float sum = 0.0f;
                int curd = sDstC[rs];
                for (int r = rs; r < re; r++) {
                    int dn = sDstC[r];
                    if (dn != curd) {
                        atomicAdd(&g_agg[(size_t)curd * H + col], sum);
                        sum = 0.0f;
                        curd = dn;
                    }
                    sum += Zs[r * ZSTR + col];
                }
                atomicAdd(&g_agg[(size_t)curd * H + col], sum);
            }
        }
    }
}

// ---------------- residual update ----------------
__global__ void k_update() {
    int i = blockIdx.x * blockDim.x + threadIdx.x;
    if (i >= NN * H) return;
    float a = g_agg[i];
    g_agg[i] = 0.0f;
    g_h[i] += a;
}

// ---------------- decoder ----------------
__global__ void k_decoder(const float* __restrict__ w1, const float* __restrict__ b1,
                          const float* __restrict__ w2, const float* __restrict__ b2,
                          const float* __restrict__ w3, const float* __restrict__ b3,
                          float* __restrict__ out) {
    int node = blockIdx.x;
    int j = threadIdx.x;
    __shared__ float sh[H];
    __shared__ float st1[H];
    __shared__ float st2[64];
    sh[j] = g_h[node * H + j];
    __syncthreads();
    float a = b1[j];
#pragma unroll 8
    for (int k = 0; k < H; k++) a += sh[k] * w1[k * H + j];
    st1[j] = silu_f(a);
    __syncthreads();
    if (j < 64) {
        float a2 = b2[j];
#pragma unroll 8
        for (int k = 0; k < H; k++) a2 += st1[k] * w2[k * 64 + j];
        st2[j] = silu_f(a2);
    }
    __syncthreads();
    if (j < FOUT) {
        float a3 = b3[j];
#pragma unroll
        for (int k = 0; k < 64; k++) a3 += st2[k] * w3[k * FOUT + j];
        out[node * FOUT + j] = a3;
    }
}

// ---------------- launch ----------------
extern "C" void kernel_launch(void* const* d_in, const int* in_sizes, int n_in,
                              void* d_out, int out_size) {
    const float* x      = (const float*)d_in[0];
    const void*  ei     = d_in[1];
    const float* ea     = (const float*)d_in[2];
    const float* enc_w1 = (const float*)d_in[3];
    const float* enc_b1 = (const float*)d_in[4];
    const float* enc_w2 = (const float*)d_in[5];
    const float* enc_b2 = (const float*)d_in[6];
    const float* conv_w1 = (const float*)d_in[7];
    const float* conv_b1 = (const float*)d_in[8];
    const float* conv_w2 = (const float*)d_in[9];
    const float* conv_b2 = (const float*)d_in[10];
    const float* dec_w1 = (const float*)d_in[11];
    const float* dec_b1 = (const float*)d_in[12];
    const float* dec_w2 = (const float*)d_in[13];
    const float* dec_b2 = (const float*)d_in[14];
    const float* dec_w3 = (const float*)d_in[15];
    const float* dec_b3 = (const float*)d_in[16];

    cudaFuncSetAttribute(k_edge5, cudaFuncAttributeMaxDynamicSharedMemorySize, SMEM_EDGE);

    k_detect<<<1, 256>>>((const int*)ei);
    k_init<<<(NN * H + 255) / 256, 256>>>();
    k_convert<<<(EE + 255) / 256, 256>>>(ei);
    k_invdeg<<<(NN + 255) / 256, 256>>>();
    k_scan<<<1, 1024>>>();
    k_scatter<<<(EE + 255) / 256, 256>>>();
    {
        dim3 g(64, NLAYERS);
        k_prepw<<<g, 256>>>(conv_w2);
    }
    k_encoder<<<NN, H>>>(x, enc_w1, enc_b1, enc_w2, enc_b2);

    const int nTiles = (NN + 127) / 128;
    for (int l = 0; l < NLAYERS; l++) {
        k_nodeproj<<<nTiles * 2, 256>>>(conv_w1 + (size_t)l * 259 * H);
        k_edge5<<<GRID_EDGE, 512, SMEM_EDGE>>>(ea, l,
                                               conv_w1 + (size_t)l * 259 * H,
                                               conv_b1 + (size_t)l * H,
                                               conv_b2 + (size_t)l * H);
        k_update<<<(NN * H + 255) / 256, 256>>>();
    }

    k_decoder<<<NN, H>>>(dec_w1, dec_b1, dec_w2, dec_b2, dec_w3, dec_b3, (float*)d_out);
}

// round 7
// speedup vs baseline: 4.4220x; 1.3905x over previous
#include <cuda_runtime.h>
#include <cstdint>

#define NN 20000
#define EE 320000
#define H 128
#define FIN 14
#define FOUT 9
#define NLAYERS 6
#define TE 128
#define SA 132     // fp32 GEMM smem stride
#define ZST 132    // edgesum Zs stride (16B-aligned rows)

// ---------------- device scratch ----------------
__device__ float g_h[NN * H];
__device__ float g_zsum[NN * H];
__device__ float g_P[NN * 256];
__device__ float g_invdeg[NN];
__device__ int   g_src[EE];
__device__ int   g_dst[EE];
__device__ int   g_cnt[NN];
__device__ int   g_off[NN + 1];
__device__ int   g_ssrc[EE];
__device__ int   g_sdst[EE];
__device__ int   g_sperm[EE];
__device__ int   g_is64;

// FFMA-only silu: x * sigmoid(x); exp via 2^t bit-trick, rcp via Newton.
__device__ __forceinline__ float fast_silu(float x) {
    float t = fminf(fmaxf(x * 1.442695041f, -126.0f), 126.0f);  // log2(e^x)
    float fi = rintf(t);
    float f = t - fi;                       // f in [-0.5, 0.5]
    float p = 1.5403530e-4f;                // 2^f Taylor deg 6, err ~1.4e-7
    p = fmaf(p, f, 1.3333558e-3f);
    p = fmaf(p, f, 9.6181291e-3f);
    p = fmaf(p, f, 5.5504109e-2f);
    p = fmaf(p, f, 2.4022651e-1f);
    p = fmaf(p, f, 6.9314718e-1f);
    p = fmaf(p, f, 1.0f);
    float sc = __int_as_float(((int)fi + 127) << 23);
    float ex = p * sc;                      // e^x
    float den = 1.0f + ex;
    float y = __int_as_float(0x7EF311C3u - __float_as_int(den));  // ~rcp
    y = y * fmaf(-den, y, 2.0f);
    y = y * fmaf(-den, y, 2.0f);
    y = y * fmaf(-den, y, 2.0f);            // rel err ~1e-10
    return x * ex * y;                      // x * e^x/(1+e^x)
}

// ---------------- preprocessing ----------------
__global__ void k_detect(const int* __restrict__ ei) {
    __shared__ int cnt;
    if (threadIdx.x == 0) cnt = 0;
    __syncthreads();
    int c = 0;
    for (int i = threadIdx.x; i < 1024; i += 256)
        if (ei[2 * i + 1] != 0) c++;
    if (c) atomicAdd(&cnt, c);
    __syncthreads();
    if (threadIdx.x == 0) g_is64 = (cnt == 0) ? 1 : 0;
}

__global__ void k_init() {
    int i = blockIdx.x * blockDim.x + threadIdx.x;
    if (i < NN * H) g_zsum[i] = 0.0f;
    if (i < NN) g_cnt[i] = 0;
}

__global__ void k_convert(const void* __restrict__ ei) {
    int i = blockIdx.x * blockDim.x + threadIdx.x;
    if (i >= EE) return;
    int s, d;
    if (g_is64) {
        const long long* p = (const long long*)ei;
        s = (int)p[i];
        d = (int)p[EE + i];
    } else {
        const int* p = (const int*)ei;
        s = p[i];
        d = p[EE + i];
    }
    g_src[i] = s;
    g_dst[i] = d;
    atomicAdd(&g_cnt[d], 1);
}

__global__ void k_invdeg() {
    int i = blockIdx.x * blockDim.x + threadIdx.x;
    if (i < NN) g_invdeg[i] = 1.0f / fmaxf((float)g_cnt[i], 1.0f);
}

__global__ void k_scan() {
    __shared__ int buf[1024];
    __shared__ int carry;
    if (threadIdx.x == 0) carry = 0;
    __syncthreads();
    for (int base = 0; base < NN; base += 1024) {
        int i = base + threadIdx.x;
        int v = (i < NN) ? g_cnt[i] : 0;
        buf[threadIdx.x] = v;
        __syncthreads();
        for (int s = 1; s < 1024; s <<= 1) {
            int t = (threadIdx.x >= s) ? buf[threadIdx.x - s] : 0;
            __syncthreads();
            buf[threadIdx.x] += t;
            __syncthreads();
        }
        if (i < NN) {
            g_off[i] = carry + buf[threadIdx.x] - v;
            g_cnt[i] = 0;
        }
        __syncthreads();
        if (threadIdx.x == 1023) carry += buf[1023];
        __syncthreads();
    }
    if (threadIdx.x == 0) g_off[NN] = EE;
}

__global__ void k_scatter() {
    int e = blockIdx.x * blockDim.x + threadIdx.x;
    if (e >= EE) return;
    int d = g_dst[e];
    int pos = g_off[d] + atomicAdd(&g_cnt[d], 1);
    g_ssrc[pos] = g_src[e];
    g_sdst[pos] = d;
    g_sperm[pos] = e;
    // note: after this kernel g_cnt[d] == deg(d) again (used by k_aggmlp)
}

// ---------------- encoder ----------------
__global__ void k_encoder(const float* __restrict__ x,
                          const float* __restrict__ w1, const float* __restrict__ b1,
                          const float* __restrict__ w2, const float* __restrict__ b2) {
    int node = blockIdx.x;
    int j = threadIdx.x;
    __shared__ float sx[FIN];
    __shared__ float sz[H];
    if (j < FIN) sx[j] = x[node * FIN + j];
    __syncthreads();
    float a = b1[j];
#pragma unroll
    for (int k = 0; k < FIN; k++) a += sx[k] * w1[k * H + j];
    sz[j] = fast_silu(a);
    __syncthreads();
    float a2 = b2[j];
#pragma unroll 8
    for (int k = 0; k < H; k++) a2 += sz[k] * w2[k * H + j];
    g_h[node * H + j] = a2;
}

// ---------------- node projection: P = h @ [W1a | W1b] (fp32) ------------
__global__ void __launch_bounds__(256, 2)
k_nodeproj(const float* __restrict__ W1) {
    __shared__ float As[32 * SA];
    __shared__ float Bs[32 * SA];
    const int tile = blockIdx.x >> 1;
    const int half = blockIdx.x & 1;
    const int n0 = tile * 128;
    const int tid = threadIdx.x;
    const int tx = tid & 15, ty = tid >> 4;
    const int row0 = ty * 8, col0 = tx * 8;

    float acc[8][8];
#pragma unroll
    for (int r = 0; r < 8; r++)
#pragma unroll
        for (int c = 0; c < 8; c++) acc[r][c] = 0.0f;

    for (int t = 0; t < 4; t++) {
#pragma unroll
        for (int it = 0; it < 4; ++it) {
            int i = tid + it * 256;
            int idx = i >> 3, seg = i & 7;
            int node = n0 + idx;
            float4 v = make_float4(0.f, 0.f, 0.f, 0.f);
            if (node < NN) v = *(const float4*)&g_h[node * H + t * 32 + seg * 4];
            As[(seg * 4 + 0) * SA + idx] = v.x;
            As[(seg * 4 + 1) * SA + idx] = v.y;
            As[(seg * 4 + 2) * SA + idx] = v.z;
            As[(seg * 4 + 3) * SA + idx] = v.w;
        }
#pragma unroll
        for (int it = 0; it < 4; ++it) {
            int i = tid + it * 256;
            int rowk = i >> 5, c4 = i & 31;
            *(float4*)&Bs[rowk * SA + c4 * 4] =
                *(const float4*)&W1[(half * 128 + t * 32 + rowk) * H + c4 * 4];
        }
        __syncthreads();
#pragma unroll 4
        for (int kk = 0; kk < 32; ++kk) {
            float4 a0 = *(const float4*)&As[kk * SA + row0];
            float4 a1 = *(const float4*)&As[kk * SA + row0 + 4];
            float4 b0 = *(const float4*)&Bs[kk * SA + col0];
            float4 b1v = *(const float4*)&Bs[kk * SA + col0 + 4];
            float av[8] = {a0.x, a0.y, a0.z, a0.w, a1.x, a1.y, a1.z, a1.w};
            float bv[8] = {b0.x, b0.y, b0.z, b0.w, b1v.x, b1v.y, b1v.z, b1v.w};
#pragma unroll
            for (int r = 0; r < 8; r++)
#pragma unroll
                for (int c = 0; c < 8; c++) acc[r][c] += av[r] * bv[c];
        }
        __syncthreads();
    }

#pragma unroll
    for (int r = 0; r < 8; r++) {
        int node = n0 + row0 + r;
        if (node < NN) {
            float* dst = &g_P[(size_t)node * 256 + half * 128 + col0];
            *(float4*)dst = make_float4(acc[r][0], acc[r][1], acc[r][2], acc[r][3]);
            *(float4*)(dst + 4) = make_float4(acc[r][4], acc[r][5], acc[r][6], acc[r][7]);
        }
    }
}

// ---------------- edge sum: zsum[dst] += silu(Pa[dst]+Pb[src]+ea*W1c+b1) --
#define ES_OFF_ZS   0
#define ES_OFF_DST  (128 * ZST * 4)            // 67584
#define ES_OFF_SRC  (ES_OFF_DST + 512)
#define ES_OFF_EA   (ES_OFF_SRC + 512)
#define ES_OFF_W1C  (ES_OFF_EA + 1536)
#define ES_OFF_B1   (ES_OFF_W1C + 1536)
#define ES_SMEM     (ES_OFF_B1 + 512)

__global__ void __launch_bounds__(256, 3)
k_edgesum(const float* __restrict__ ea,
          const float* __restrict__ W1, const float* __restrict__ b1) {
    extern __shared__ char smb[];
    float* Zs   = (float*)(smb + ES_OFF_ZS);
    int*   sDst = (int*)(smb + ES_OFF_DST);
    int*   sSrc = (int*)(smb + ES_OFF_SRC);
    float* sEa  = (float*)(smb + ES_OFF_EA);
    float* sW1c = (float*)(smb + ES_OFF_W1C);
    float* sB1  = (float*)(smb + ES_OFF_B1);

    const int tid = threadIdx.x;
    const int e0 = blockIdx.x * TE;

    if (tid < TE) {
        sDst[tid] = g_sdst[e0 + tid];
        sSrc[tid] = g_ssrc[e0 + tid];
        int p = g_sperm[e0 + tid];
        sEa[tid * 3 + 0] = ea[p * 3 + 0];
        sEa[tid * 3 + 1] = ea[p * 3 + 1];
        sEa[tid * 3 + 2] = ea[p * 3 + 2];
        sB1[tid] = b1[tid];
    }
    for (int i = tid; i < 3 * H; i += 256)
        sW1c[i] = W1[(256 + i / H) * H + (i % H)];
    __syncthreads();

    // z1 elementwise: 2 threads per edge (64 cols each)
    {
        const int edge = tid >> 1;
        const int ch0 = (tid & 1) * 64;
        const float* pa = &g_P[(size_t)sDst[edge] * 256 + ch0];
        const float* pb = &g_P[(size_t)sSrc[edge] * 256 + 128 + ch0];
        float ev0 = sEa[edge * 3 + 0], ev1 = sEa[edge * 3 + 1], ev2 = sEa[edge * 3 + 2];
#pragma unroll
        for (int q = 0; q < 16; q++) {
            int c = ch0 + q * 4;
            float4 va = *(const float4*)&pa[q * 4];
            float4 vb = *(const float4*)&pb[q * 4];
            float z0 = fast_silu(va.x + vb.x + ev0 * sW1c[c + 0] + ev1 * sW1c[128 + c + 0] + ev2 * sW1c[256 + c + 0] + sB1[c + 0]);
            float z1 = fast_silu(va.y + vb.y + ev0 * sW1c[c + 1] + ev1 * sW1c[128 + c + 1] + ev2 * sW1c[256 + c + 1] + sB1[c + 1]);
            float z2 = fast_silu(va.z + vb.z + ev0 * sW1c[c + 2] + ev1 * sW1c[128 + c + 2] + ev2 * sW1c[256 + c + 2] + sB1[c + 2]);
            float z3 = fast_silu(va.w + vb.w + ev0 * sW1c[c + 3] + ev1 * sW1c[128 + c + 3] + ev2 * sW1c[256 + c + 3] + sB1[c + 3]);
            *(float4*)&Zs[edge * ZST + c] = make_float4(z0, z1, z2, z3);
        }
    }
    __syncthreads();

    // segmented reduce by dst (sorted); boundary atomics
    {
        const int col = tid & 127;
        const int seg = tid >> 7;
        const int rs = seg * 64, re = rs + 64;
        float sum = 0.0f;
        int cur = sDst[rs];
        for (int r = rs; r < re; r++) {
            int dn = sDst[r];
            if (dn != cur) {
                atomicAdd(&g_zsum[(size_t)cur * H + col], sum);
                sum = 0.0f;
                cur = dn;
            }
            sum += Zs[r * ZST + col];
        }
        atomicAdd(&g_zsum[(size_t)cur * H + col], sum);
    }
}

// ---------------- agg GEMM + residual: h += (zsum*inv)@W2 + b2 ------------
__global__ void __launch_bounds__(256, 2)
k_aggmlp(const float* __restrict__ W2, const float* __restrict__ b2) {
    __shared__ float As[32 * SA];
    __shared__ float Bs[32 * SA];
    __shared__ float sInv[128];
    __shared__ float sS[128];
    __shared__ float sB2[128];
    const int n0 = blockIdx.x * 128;
    const int tid = threadIdx.x;
    const int tx = tid & 15, ty = tid >> 4;
    const int row0 = ty * 8, col0 = tx * 8;

    if (tid < 128) {
        int node = n0 + tid;
        sInv[tid] = (node < NN) ? g_invdeg[node] : 1.0f;
        sS[tid]   = (node < NN && g_cnt[node] > 0) ? 1.0f : 0.0f;
        sB2[tid]  = b2[tid];
    }
    __syncthreads();

    float acc[8][8];
#pragma unroll
    for (int r = 0; r < 8; r++)
#pragma unroll
        for (int c = 0; c < 8; c++) acc[r][c] = 0.0f;

    for (int t = 0; t < 4; t++) {
#pragma unroll
        for (int it = 0; it < 4; ++it) {
            int i = tid + it * 256;
            int idx = i >> 3, seg = i & 7;
            int node = n0 + idx;
            float4 v = make_float4(0.f, 0.f, 0.f, 0.f);
            if (node < NN) v = *(const float4*)&g_zsum[(size_t)node * H + t * 32 + seg * 4];
            float iv = sInv[idx];
            As[(seg * 4 + 0) * SA + idx] = v.x * iv;
            As[(seg * 4 + 1) * SA + idx] = v.y * iv;
            As[(seg * 4 + 2) * SA + idx] = v.z * iv;
            As[(seg * 4 + 3) * SA + idx] = v.w * iv;
        }
#pragma unroll
        for (int it = 0; it < 4; ++it) {
            int i = tid + it * 256;
            int rowk = i >> 5, c4 = i & 31;
            *(float4*)&Bs[rowk * SA + c4 * 4] =
                *(const float4*)&W2[(t * 32 + rowk) * H + c4 * 4];
        }
        __syncthreads();
#pragma unroll 4
        for (int kk = 0; kk < 32; ++kk) {
            float4 a0 = *(const float4*)&As[kk * SA + row0];
            float4 a1 = *(const float4*)&As[kk * SA + row0 + 4];
            float4 b0 = *(const float4*)&Bs[kk * SA + col0];
            float4 b1v = *(const float4*)&Bs[kk * SA + col0 + 4];
            float av[8] = {a0.x, a0.y, a0.z, a0.w, a1.x, a1.y, a1.z, a1.w};
            float bv[8] = {b0.x, b0.y, b0.z, b0.w, b1v.x, b1v.y, b1v.z, b1v.w};
#pragma unroll
            for (int r = 0; r < 8; r++)
#pragma unroll
                for (int c = 0; c < 8; c++) acc[r][c] += av[r] * bv[c];
        }
        __syncthreads();
    }

    // epilogue: h += acc + b2*s ; zsum = 0
#pragma unroll
    for (int r = 0; r < 8; r++) {
        int node = n0 + row0 + r;
        if (node < NN) {
            float s = sS[row0 + r];
            float* hp = &g_h[(size_t)node * H + col0];
            float* zp = &g_zsum[(size_t)node * H + col0];
            float4 h0 = *(float4*)hp;
            float4 h1 = *(float4*)(hp + 4);
            h0.x += acc[r][0] + sB2[col0 + 0] * s;
            h0.y += acc[r][1] + sB2[col0 + 1] * s;
            h0.z += acc[r][2] + sB2[col0 + 2] * s;
            h0.w += acc[r][3] + sB2[col0 + 3] * s;
            h1.x += acc[r][4] + sB2[col0 + 4] * s;
            h1.y += acc[r][5] + sB2[col0 + 5] * s;
            h1.z += acc[r][6] + sB2[col0 + 6] * s;
            h1.w += acc[r][7] + sB2[col0 + 7] * s;
            *(float4*)hp = h0;
            *(float4*)(hp + 4) = h1;
            *(float4*)zp = make_float4(0.f, 0.f, 0.f, 0.f);
            *(float4*)(zp + 4) = make_float4(0.f, 0.f, 0.f, 0.f);
        }
    }
}

// ---------------- decoder ----------------
__global__ void k_decoder(const float* __restrict__ w1, const float* __restrict__ b1,
                          const float* __restrict__ w2, const float* __restrict__ b2,
                          const float* __restrict__ w3, const float* __restrict__ b3,
                          float* __restrict__ out) {
    int node = blockIdx.x;
    int j = threadIdx.x;
    __shared__ float sh[H];
    __shared__ float st1[H];
    __shared__ float st2[64];
    sh[j] = g_h[node * H + j];
    __syncthreads();
    float a = b1[j];
#pragma unroll 8
    for (int k = 0; k < H; k++) a += sh[k] * w1[k * H + j];
    st1[j] = fast_silu(a);
    __syncthreads();
    if (j < 64) {
        float a2 = b2[j];
#pragma unroll 8
        for (int k = 0; k < H; k++) a2 += st1[k] * w2[k * 64 + j];
        st2[j] = fast_silu(a2);
    }
    __syncthreads();
    if (j < FOUT) {
        float a3 = b3[j];
#pragma unroll
        for (int k = 0; k < 64; k++) a3 += st2[k] * w3[k * FOUT + j];
        out[node * FOUT + j] = a3;
    }
}

// ---------------- launch ----------------
extern "C" void kernel_launch(void* const* d_in, const int* in_sizes, int n_in,
                              void* d_out, int out_size) {
    const float* x      = (const float*)d_in[0];
    const void*  ei     = d_in[1];
    const float* ea     = (const float*)d_in[2];
    const float* enc_w1 = (const float*)d_in[3];
    const float* enc_b1 = (const float*)d_in[4];
    const float* enc_w2 = (const float*)d_in[5];
    const float* enc_b2 = (const float*)d_in[6];
    const float* conv_w1 = (const float*)d_in[7];
    const float* conv_b1 = (const float*)d_in[8];
    const float* conv_w2 = (const float*)d_in[9];
    const float* conv_b2 = (const float*)d_in[10];
    const float* dec_w1 = (const float*)d_in[11];
    const float* dec_b1 = (const float*)d_in[12];
    const float* dec_w2 = (const float*)d_in[13];
    const float* dec_b2 = (const float*)d_in[14];
    const float* dec_w3 = (const float*)d_in[15];
    const float* dec_b3 = (const float*)d_in[16];

    cudaFuncSetAttribute(k_edgesum, cudaFuncAttributeMaxDynamicSharedMemorySize, ES_SMEM);

    k_detect<<<1, 256>>>((const int*)ei);
    k_init<<<(NN * H + 255) / 256, 256>>>();
    k_convert<<<(EE + 255) / 256, 256>>>(ei);
    k_invdeg<<<(NN + 255) / 256, 256>>>();
    k_scan<<<1, 1024>>>();
    k_scatter<<<(EE + 255) / 256, 256>>>();
    k_encoder<<<NN, H>>>(x, enc_w1, enc_b1, enc_w2, enc_b2);

    const int nTiles = (NN + 127) / 128;  // 157
    for (int l = 0; l < NLAYERS; l++) {
        k_nodeproj<<<nTiles * 2, 256>>>(conv_w1 + (size_t)l * 259 * H);
        k_edgesum<<<EE / TE, 256, ES_SMEM>>>(ea,
                                             conv_w1 + (size_t)l * 259 * H,
                                             conv_b1 + (size_t)l * H);
        k_aggmlp<<<nTiles, 256>>>(conv_w2 + (size_t)l * H * H,
                                  conv_b2 + (size_t)l * H);
    }

    k_decoder<<<NN, H>>>(dec_w1, dec_b1, dec_w2, dec_b2, dec_w3, dec_b3, (float*)d_out);
}

// round 8
// speedup vs baseline: 6.2123x; 1.4048x over previous
#include <cuda_runtime.h>
#include <cstdint>

#define NN 20000
#define EE 320000
#define H 128
#define FIN 14
#define FOUT 9
#define NLAYERS 6
#define SA 132
#define NM 132

// ---------------- device scratch ----------------
__device__ float g_h[NN * H];
__device__ float g_zsum[NN * H];
__device__ float g_P[NN * 256];
__device__ float g_invdeg[NN];
__device__ int   g_src[EE];
__device__ int   g_dst[EE];
__device__ int   g_cnt[NN];
__device__ int   g_off[NN + 1];
__device__ int   g_ssrc[EE];
__device__ float4 g_sea[EE];          // dst-sorted edge_attr (padded to 4)
__device__ int   g_is64;

__device__ __forceinline__ float silu_m(float x) {
    return __fdividef(x, 1.0f + __expf(-x));   // 2 MUFU + few FMA
}

// ---------------- preprocessing ----------------
__global__ void k_detect(const int* __restrict__ ei) {
    __shared__ int cnt;
    if (threadIdx.x == 0) cnt = 0;
    __syncthreads();
    int c = 0;
    for (int i = threadIdx.x; i < 1024; i += 256)
        if (ei[2 * i + 1] != 0) c++;
    if (c) atomicAdd(&cnt, c);
    __syncthreads();
    if (threadIdx.x == 0) g_is64 = (cnt == 0) ? 1 : 0;
}

__global__ void k_init() {
    int i = blockIdx.x * blockDim.x + threadIdx.x;
    if (i < NN) g_cnt[i] = 0;
}

__global__ void k_convert(const void* __restrict__ ei) {
    int i = blockIdx.x * blockDim.x + threadIdx.x;
    if (i >= EE) return;
    int s, d;
    if (g_is64) {
        const long long* p = (const long long*)ei;
        s = (int)p[i];
        d = (int)p[EE + i];
    } else {
        const int* p = (const int*)ei;
        s = p[i];
        d = p[EE + i];
    }
    g_src[i] = s;
    g_dst[i] = d;
    atomicAdd(&g_cnt[d], 1);
}

__global__ void k_invdeg() {
    int i = blockIdx.x * blockDim.x + threadIdx.x;
    if (i < NN) g_invdeg[i] = 1.0f / fmaxf((float)g_cnt[i], 1.0f);
}

// shuffle-based exclusive scan of g_cnt -> g_off; reset g_cnt
__global__ void k_scan() {
    __shared__ int wsum[32];
    __shared__ int carry;
    const int lane = threadIdx.x & 31;
    const int wp = threadIdx.x >> 5;
    if (threadIdx.x == 0) carry = 0;
    __syncthreads();
    for (int base = 0; base < NN; base += 1024) {
        int i = base + threadIdx.x;
        int v = (i < NN) ? g_cnt[i] : 0;
        int s = v;
#pragma unroll
        for (int dlt = 1; dlt < 32; dlt <<= 1) {
            int t = __shfl_up_sync(0xFFFFFFFFu, s, dlt);
            if (lane >= dlt) s += t;
        }
        __syncthreads();                 // wsum safe from prev iteration
        if (lane == 31) wsum[wp] = s;
        __syncthreads();
        if (wp == 0) {
            int ws = wsum[lane];
#pragma unroll
            for (int dlt = 1; dlt < 32; dlt <<= 1) {
                int t = __shfl_up_sync(0xFFFFFFFFu, ws, dlt);
                if (lane >= dlt) ws += t;
            }
            wsum[lane] = ws;
        }
        __syncthreads();
        int excl = carry + s - v + (wp > 0 ? wsum[wp - 1] : 0);
        if (i < NN) { g_off[i] = excl; g_cnt[i] = 0; }
        __syncthreads();                 // everyone has read carry/wsum
        if (threadIdx.x == 0) carry += wsum[31];
    }
    if (threadIdx.x == 0) g_off[NN] = EE;
}

__global__ void k_scatter(const float* __restrict__ ea) {
    int e = blockIdx.x * blockDim.x + threadIdx.x;
    if (e >= EE) return;
    int d = g_dst[e];
    int pos = g_off[d] + atomicAdd(&g_cnt[d], 1);
    g_ssrc[pos] = g_src[e];
    float4 v;
    v.x = ea[e * 3 + 0];
    v.y = ea[e * 3 + 1];
    v.z = ea[e * 3 + 2];
    v.w = 0.0f;
    g_sea[pos] = v;
    // after this kernel g_cnt[d] == deg(d) again (mask source for k_nodemlp)
}

// ---------------- tiled encoder (128 nodes/block) ----------------
#define EN_XS 0
#define EN_W1 (EN_XS + FIN * NM * 4)          // 7392
#define EN_TS (EN_W1 + FIN * H * 4)           // 14560
#define EN_BS (EN_TS + H * NM * 4)            // 82144
#define EN_B1 (EN_BS + 32 * NM * 4)           // 99040
#define EN_B2 (EN_B1 + 512)                   // 99552
#define EN_SMEM (EN_B2 + 512)                 // 100064

__global__ void __launch_bounds__(256, 2)
k_encoder2(const float* __restrict__ x,
           const float* __restrict__ w1, const float* __restrict__ b1,
           const float* __restrict__ w2, const float* __restrict__ b2) {
    extern __shared__ char smb[];
    float* Xs  = (float*)(smb + EN_XS);
    float* W1s = (float*)(smb + EN_W1);
    float* Ts  = (float*)(smb + EN_TS);
    float* Bs  = (float*)(smb + EN_BS);
    float* sB1 = (float*)(smb + EN_B1);
    float* sB2 = (float*)(smb + EN_B2);
    const int n0 = blockIdx.x * 128;
    const int tid = threadIdx.x;
    const int tx = tid & 15, ty = tid >> 4;
    const int row0 = ty * 8, col0 = tx * 8;

    for (int i = tid; i < FIN * 128; i += 256) {
        int k = i >> 7, nd = i & 127;
        Xs[k * NM + nd] = (n0 + nd < NN) ? x[(size_t)(n0 + nd) * FIN + k] : 0.0f;
        W1s[i] = w1[i];
    }
    if (tid < 128) { sB1[tid] = b1[tid]; sB2[tid] = b2[tid]; }
    __syncthreads();

    // GEMM1 (K=14) + silu -> Ts transposed
    {
        float acc[8][8];
#pragma unroll
        for (int r = 0; r < 8; r++)
#pragma unroll
            for (int c = 0; c < 8; c++) acc[r][c] = 0.0f;
#pragma unroll
        for (int k = 0; k < FIN; k++) {
            float av[8], bv[8];
#pragma unroll
            for (int r = 0; r < 8; r++) av[r] = Xs[k * NM + row0 + r];
#pragma unroll
            for (int c = 0; c < 8; c++) bv[c] = W1s[k * 128 + col0 + c];
#pragma unroll
            for (int r = 0; r < 8; r++)
#pragma unroll
                for (int c = 0; c < 8; c++) acc[r][c] += av[r] * bv[c];
        }
#pragma unroll
        for (int r = 0; r < 8; r++)
#pragma unroll
            for (int c = 0; c < 8; c++)
                Ts[(col0 + c) * NM + row0 + r] = silu_m(acc[r][c] + sB1[col0 + c]);
    }
    __syncthreads();

    // GEMM2 (K=128) -> g_h
    {
        float acc[8][8];
#pragma unroll
        for (int r = 0; r < 8; r++)
#pragma unroll
            for (int c = 0; c < 8; c++) acc[r][c] = 0.0f;
        for (int t = 0; t < 4; t++) {
#pragma unroll
            for (int it = 0; it < 4; ++it) {
                int i = tid + it * 256;
                int rowk = i >> 5, c4 = i & 31;
                *(float4*)&Bs[rowk * NM + c4 * 4] =
                    *(const float4*)&w2[(size_t)(t * 32 + rowk) * H + c4 * 4];
            }
            __syncthreads();
#pragma unroll 4
            for (int kk = 0; kk < 32; ++kk) {
                float av[8], bv[8];
                int k = t * 32 + kk;
#pragma unroll
                for (int r = 0; r < 8; r++) av[r] = Ts[k * NM + row0 + r];
                float4 b0 = *(const float4*)&Bs[kk * NM + col0];
                float4 b1v = *(const float4*)&Bs[kk * NM + col0 + 4];
                bv[0] = b0.x; bv[1] = b0.y; bv[2] = b0.z; bv[3] = b0.w;
                bv[4] = b1v.x; bv[5] = b1v.y; bv[6] = b1v.z; bv[7] = b1v.w;
#pragma unroll
                for (int r = 0; r < 8; r++)
#pragma unroll
                    for (int c = 0; c < 8; c++) acc[r][c] += av[r] * bv[c];
            }
            __syncthreads();
        }
#pragma unroll
        for (int r = 0; r < 8; r++) {
            int node = n0 + row0 + r;
            if (node < NN) {
                float* hp = &g_h[(size_t)node * H + col0];
                *(float4*)hp = make_float4(acc[r][0] + sB2[col0 + 0], acc[r][1] + sB2[col0 + 1],
                                           acc[r][2] + sB2[col0 + 2], acc[r][3] + sB2[col0 + 3]);
                *(float4*)(hp + 4) = make_float4(acc[r][4] + sB2[col0 + 4], acc[r][5] + sB2[col0 + 5],
                                                 acc[r][6] + sB2[col0 + 6], acc[r][7] + sB2[col0 + 7]);
            }
        }
    }
}

// ---------------- node projection (layer 0 only) ----------------
__global__ void __launch_bounds__(256, 2)
k_nodeproj(const float* __restrict__ W1) {
    __shared__ float As[32 * SA];
    __shared__ float Bs[32 * SA];
    const int tile = blockIdx.x >> 1;
    const int half = blockIdx.x & 1;
    const int n0 = tile * 128;
    const int tid = threadIdx.x;
    const int tx = tid & 15, ty = tid >> 4;
    const int row0 = ty * 8, col0 = tx * 8;

    float acc[8][8];
#pragma unroll
    for (int r = 0; r < 8; r++)
#pragma unroll
        for (int c = 0; c < 8; c++) acc[r][c] = 0.0f;

    for (int t = 0; t < 4; t++) {
#pragma unroll
        for (int it = 0; it < 4; ++it) {
            int i = tid + it * 256;
            int idx = i >> 3, seg = i & 7;
            int node = n0 + idx;
            float4 v = make_float4(0.f, 0.f, 0.f, 0.f);
            if (node < NN) v = *(const float4*)&g_h[(size_t)node * H + t * 32 + seg * 4];
            As[(seg * 4 + 0) * SA + idx] = v.x;
            As[(seg * 4 + 1) * SA + idx] = v.y;
            As[(seg * 4 + 2) * SA + idx] = v.z;
            As[(seg * 4 + 3) * SA + idx] = v.w;
        }
#pragma unroll
        for (int it = 0; it < 4; ++it) {
            int i = tid + it * 256;
            int rowk = i >> 5, c4 = i & 31;
            *(float4*)&Bs[rowk * SA + c4 * 4] =
                *(const float4*)&W1[(size_t)(half * 128 + t * 32 + rowk) * H + c4 * 4];
        }
        __syncthreads();
#pragma unroll 4
        for (int kk = 0; kk < 32; ++kk) {
            float4 a0 = *(const float4*)&As[kk * SA + row0];
            float4 a1 = *(const float4*)&As[kk * SA + row0 + 4];
            float4 b0 = *(const float4*)&Bs[kk * SA + col0];
            float4 b1v = *(const float4*)&Bs[kk * SA + col0 + 4];
            float av[8] = {a0.x, a0.y, a0.z, a0.w, a1.x, a1.y, a1.z, a1.w};
            float bv[8] = {b0.x, b0.y, b0.z, b0.w, b1v.x, b1v.y, b1v.z, b1v.w};
#pragma unroll
            for (int r = 0; r < 8; r++)
#pragma unroll
                for (int c = 0; c < 8; c++) acc[r][c] += av[r] * bv[c];
        }
        __syncthreads();
    }

#pragma unroll
    for (int r = 0; r < 8; r++) {
        int node = n0 + row0 + r;
        if (node < NN) {
            float* dst = &g_P[(size_t)node * 256 + half * 128 + col0];
            *(float4*)dst = make_float4(acc[r][0], acc[r][1], acc[r][2], acc[r][3]);
            *(float4*)(dst + 4) = make_float4(acc[r][4], acc[r][5], acc[r][6], acc[r][7]);
        }
    }
}

// ---------------- CSR edge sum: warp per node, no smem/atomics -----------
__global__ void __launch_bounds__(256)
k_edgesum(const float* __restrict__ W1, const float* __restrict__ b1) {
    const int node = blockIdx.x * 8 + (threadIdx.x >> 5);
    if (node >= NN) return;
    const int lid = threadIdx.x & 31;
    const int c = lid * 4;
    const float4 wa = *(const float4*)&W1[256 * H + c];
    const float4 wb = *(const float4*)&W1[257 * H + c];
    const float4 wc = *(const float4*)&W1[258 * H + c];
    const float4 bb = *(const float4*)&b1[c];
    const float4 pa = *(const float4*)&g_P[(size_t)node * 256 + c];
    const float bx = pa.x + bb.x, by = pa.y + bb.y;
    const float bz = pa.z + bb.z, bw = pa.w + bb.w;
    float4 acc = make_float4(0.f, 0.f, 0.f, 0.f);
    int e = g_off[node];
    const int end = g_off[node + 1];
    if (e < end) {
        int src = g_ssrc[e];
        float4 eav = g_sea[e];
        float4 pb = *(const float4*)&g_P[(size_t)src * 256 + 128 + c];
        while (e < end) {
            const int en = e + 1;
            int srcN = src; float4 eavN = eav; float4 pbN = pb;
            if (en < end) {
                srcN = g_ssrc[en];
                eavN = g_sea[en];
                pbN = *(const float4*)&g_P[(size_t)srcN * 256 + 128 + c];
            }
            float v0 = bx + pb.x + eav.x * wa.x + eav.y * wb.x + eav.z * wc.x;
            float v1 = by + pb.y + eav.x * wa.y + eav.y * wb.y + eav.z * wc.y;
            float v2 = bz + pb.z + eav.x * wa.z + eav.y * wb.z + eav.z * wc.z;
            float v3 = bw + pb.w + eav.x * wa.w + eav.y * wb.w + eav.z * wc.w;
            acc.x += silu_m(v0);
            acc.y += silu_m(v1);
            acc.z += silu_m(v2);
            acc.w += silu_m(v3);
            e = en; src = srcN; eav = eavN; pb = pbN;
        }
    }
    const float iv = g_invdeg[node];
    acc.x *= iv; acc.y *= iv; acc.z *= iv; acc.w *= iv;
    *(float4*)&g_zsum[(size_t)node * H + c] = acc;
}

// ---------------- fused agg-GEMM + residual + next-layer projection ------
#define NM_AS 0
#define NM_BS (NM_AS + 32 * NM * 4)       // 16896
#define NM_HS (NM_BS + 32 * NM * 4)       // 33792
#define NM_B2 (NM_HS + 128 * NM * 4)      // 101376
#define NM_MK (NM_B2 + 512)               // 101888
#define NM_SMEM (NM_MK + 512)             // 102400

__global__ void __launch_bounds__(256, 2)
k_nodemlp(const float* __restrict__ W2, const float* __restrict__ b2,
          const float* __restrict__ W1n, int do_proj) {
    extern __shared__ char smb[];
    float* As  = (float*)(smb + NM_AS);
    float* Bs  = (float*)(smb + NM_BS);
    float* Hs  = (float*)(smb + NM_HS);
    float* sB2 = (float*)(smb + NM_B2);
    float* sMk = (float*)(smb + NM_MK);
    const int n0 = blockIdx.x * 128;
    const int tid = threadIdx.x;
    const int tx = tid & 15, ty = tid >> 4;
    const int row0 = ty * 8, col0 = tx * 8;

    if (tid < 128) {
        int node = n0 + tid;
        sMk[tid] = (node < NN && g_cnt[node] > 0) ? 1.0f : 0.0f;
        sB2[tid] = b2[tid];
    }

    // ---- phase A: acc = zsum_scaled @ W2
    float acc[8][8];
#pragma unroll
    for (int r = 0; r < 8; r++)
#pragma unroll
        for (int c = 0; c < 8; c++) acc[r][c] = 0.0f;

    for (int t = 0; t < 4; t++) {
#pragma unroll
        for (int it = 0; it < 4; ++it) {
            int i = tid + it * 256;
            int idx = i >> 3, seg = i & 7;
            int node = n0 + idx;
            float4 v = make_float4(0.f, 0.f, 0.f, 0.f);
            if (node < NN) v = *(const float4*)&g_zsum[(size_t)node * H + t * 32 + seg * 4];
            As[(seg * 4 + 0) * NM + idx] = v.x;
            As[(seg * 4 + 1) * NM + idx] = v.y;
            As[(seg * 4 + 2) * NM + idx] = v.z;
            As[(seg * 4 + 3) * NM + idx] = v.w;
        }
#pragma unroll
        for (int it = 0; it < 4; ++it) {
            int i = tid + it * 256;
            int rowk = i >> 5, c4 = i & 31;
            *(float4*)&Bs[rowk * NM + c4 * 4] =
                *(const float4*)&W2[(size_t)(t * 32 + rowk) * H + c4 * 4];
        }
        __syncthreads();
#pragma unroll 4
        for (int kk = 0; kk < 32; ++kk) {
            float4 a0 = *(const float4*)&As[kk * NM + row0];
            float4 a1 = *(const float4*)&As[kk * NM + row0 + 4];
            float4 b0 = *(const float4*)&Bs[kk * NM + col0];
            float4 b1v = *(const float4*)&Bs[kk * NM + col0 + 4];
            float av[8] = {a0.x, a0.y, a0.z, a0.w, a1.x, a1.y, a1.z, a1.w};
            float bv[8] = {b0.x, b0.y, b0.z, b0.w, b1v.x, b1v.y, b1v.z, b1v.w};
#pragma unroll
            for (int r = 0; r < 8; r++)
#pragma unroll
                for (int c = 0; c < 8; c++) acc[r][c] += av[r] * bv[c];
        }
        __syncthreads();
    }

    // ---- epilogue: h_new = h + acc + b2*mask -> g_h and Hs (transposed)
#pragma unroll
    for (int r = 0; r < 8; r++) {
        int rr = row0 + r;
        int node = n0 + rr;
        if (node < NN) {
            float m = sMk[rr];
            float* hp = &g_h[(size_t)node * H + col0];
            float4 h0 = *(float4*)hp;
            float4 h1 = *(float4*)(hp + 4);
            float hn[8];
            hn[0] = h0.x + acc[r][0] + sB2[col0 + 0] * m;
            hn[1] = h0.y + acc[r][1] + sB2[col0 + 1] * m;
            hn[2] = h0.z + acc[r][2] + sB2[col0 + 2] * m;
            hn[3] = h0.w + acc[r][3] + sB2[col0 + 3] * m;
            hn[4] = h1.x + acc[r][4] + sB2[col0 + 4] * m;
            hn[5] = h1.y + acc[r][5] + sB2[col0 + 5] * m;
            hn[6] = h1.z + acc[r][6] + sB2[col0 + 6] * m;
            hn[7] = h1.w + acc[r][7] + sB2[col0 + 7] * m;
            *(float4*)hp = make_float4(hn[0], hn[1], hn[2], hn[3]);
            *(float4*)(hp + 4) = make_float4(hn[4], hn[5], hn[6], hn[7]);
#pragma unroll
            for (int c = 0; c < 8; c++) Hs[(col0 + c) * NM + rr] = hn[c];
        } else {
#pragma unroll
            for (int c = 0; c < 8; c++) Hs[(col0 + c) * NM + rr] = 0.0f;
        }
    }
    __syncthreads();

    if (!do_proj) return;

    // ---- phase B: P = h_new @ [W1a | W1b]
    for (int half = 0; half < 2; half++) {
        float pacc[8][8];
#pragma unroll
        for (int r = 0; r < 8; r++)
#pragma unroll
            for (int c = 0; c < 8; c++) pacc[r][c] = 0.0f;

        for (int t = 0; t < 4; t++) {
#pragma unroll
            for (int it = 0; it < 4; ++it) {
                int i = tid + it * 256;
                int rowk = i >> 5, c4 = i & 31;
                *(float4*)&Bs[rowk * NM + c4 * 4] =
                    *(const float4*)&W1n[(size_t)(half * 128 + t * 32 + rowk) * H + c4 * 4];
            }
            __syncthreads();
#pragma unroll 4
            for (int kk = 0; kk < 32; ++kk) {
                int k = t * 32 + kk;
                float av[8], bv[8];
#pragma unroll
                for (int r = 0; r < 8; r++) av[r] = Hs[k * NM + row0 + r];
                float4 b0 = *(const float4*)&Bs[kk * NM + col0];
                float4 b1v = *(const float4*)&Bs[kk * NM + col0 + 4];
                bv[0] = b0.x; bv[1] = b0.y; bv[2] = b0.z; bv[3] = b0.w;
                bv[4] = b1v.x; bv[5] = b1v.y; bv[6] = b1v.z; bv[7] = b1v.w;
#pragma unroll
                for (int r = 0; r < 8; r++)
#pragma unroll
                    for (int c = 0; c < 8; c++) pacc[r][c] += av[r] * bv[c];
            }
            __syncthreads();
        }
#pragma unroll
        for (int r = 0; r < 8; r++) {
            int node = n0 + row0 + r;
            if (node < NN) {
                float* dst = &g_P[(size_t)node * 256 + half * 128 + col0];
                *(float4*)dst = make_float4(pacc[r][0], pacc[r][1], pacc[r][2], pacc[r][3]);
                *(float4*)(dst + 4) = make_float4(pacc[r][4], pacc[r][5], pacc[r][6], pacc[r][7]);
            }
        }
    }
}

// ---------------- tiled decoder (128 nodes/block) ----------------
#define DE_HS 0
#define DE_BS (DE_HS + 128 * NM * 4)      // 67584
#define DE_W3 (DE_BS + 32 * NM * 4)       // 84480
#define DE_B1 (DE_W3 + 64 * FOUT * 4)     // 86784
#define DE_B2 (DE_B1 + 512)               // 87296
#define DE_B3 (DE_B2 + 256)               // 87552
#define DE_SMEM (DE_B3 + 64)              // 87616

__global__ void __launch_bounds__(256, 2)
k_decoder2(const float* __restrict__ w1, const float* __restrict__ b1,
           const float* __restrict__ w2, const float* __restrict__ b2,
           const float* __restrict__ w3, const float* __restrict__ b3,
           float* __restrict__ out) {
    extern __shared__ char smb[];
    float* Hs  = (float*)(smb + DE_HS);
    float* Bs  = (float*)(smb + DE_BS);
    float* w3s = (float*)(smb + DE_W3);
    float* sb1 = (float*)(smb + DE_B1);
    float* sb2 = (float*)(smb + DE_B2);
    float* sb3 = (float*)(smb + DE_B3);
    const int n0 = blockIdx.x * 128;
    const int tid = threadIdx.x;
    const int tx = tid & 15, ty = tid >> 4;
    const int row0 = ty * 8, col0 = tx * 8;

    // load h transposed into Hs
#pragma unroll
    for (int it = 0; it < 16; ++it) {
        int i = tid + it * 256;           // 0..4095 float4 units
        int nd = i >> 5, seg = i & 31;
        int node = n0 + nd;
        float4 v = make_float4(0.f, 0.f, 0.f, 0.f);
        if (node < NN) v = *(const float4*)&g_h[(size_t)node * H + seg * 4];
        Hs[(seg * 4 + 0) * NM + nd] = v.x;
        Hs[(seg * 4 + 1) * NM + nd] = v.y;
        Hs[(seg * 4 + 2) * NM + nd] = v.z;
        Hs[(seg * 4 + 3) * NM + nd] = v.w;
    }
    for (int i = tid; i < 64 * FOUT; i += 256) w3s[i] = w3[i];
    if (tid < 128) sb1[tid] = b1[tid];
    if (tid < 64) sb2[tid] = b2[tid];
    if (tid < FOUT) sb3[tid] = b3[tid];
    __syncthreads();

    // GEMM1 (K=128) -> t1 (in-place into Hs after sync)
    float acc[8][8];
#pragma unroll
    for (int r = 0; r < 8; r++)
#pragma unroll
        for (int c = 0; c < 8; c++) acc[r][c] = 0.0f;
    for (int t = 0; t < 4; t++) {
#pragma unroll
        for (int it = 0; it < 4; ++it) {
            int i = tid + it * 256;
            int rowk = i >> 5, c4 = i & 31;
            *(float4*)&Bs[rowk * NM + c4 * 4] =
                *(const float4*)&w1[(size_t)(t * 32 + rowk) * H + c4 * 4];
        }
        __syncthreads();
#pragma unroll 4
        for (int kk = 0; kk < 32; ++kk) {
            int k = t * 32 + kk;
            float av[8], bv[8];
#pragma unroll
            for (int r = 0; r < 8; r++) av[r] = Hs[k * NM + row0 + r];
            float4 b0 = *(const float4*)&Bs[kk * NM + col0];
            float4 b1v = *(const float4*)&Bs[kk * NM + col0 + 4];
            bv[0] = b0.x; bv[1] = b0.y; bv[2] = b0.z; bv[3] = b0.w;
            bv[4] = b1v.x; bv[5] = b1v.y; bv[6] = b1v.z; bv[7] = b1v.w;
#pragma unroll
            for (int r = 0; r < 8; r++)
#pragma unroll
                for (int c = 0; c < 8; c++) acc[r][c] += av[r] * bv[c];
        }
        __syncthreads();
    }
#pragma unroll
    for (int r = 0; r < 8; r++)
#pragma unroll
        for (int c = 0; c < 8; c++)
            Hs[(col0 + c) * NM + row0 + r] = silu_m(acc[r][c] + sb1[col0 + c]);
    __syncthreads();

    // GEMM2 (K=128, 64 cols) -> t2 (into Hs rows 0..63 after sync)
    const int col0b = tx * 4;
    float acc2[8][4];
#pragma unroll
    for (int r = 0; r < 8; r++)
#pragma unroll
        for (int c = 0; c < 4; c++) acc2[r][c] = 0.0f;
    for (int t = 0; t < 4; t++) {
#pragma unroll
        for (int it = 0; it < 2; ++it) {
            int i = tid + it * 256;       // 0..511 float4 units (32 x 64)
            int rowk = i >> 4, c4 = i & 15;
            *(float4*)&Bs[rowk * NM + c4 * 4] =
                *(const float4*)&w2[(size_t)(t * 32 + rowk) * 64 + c4 * 4];
        }
        __syncthreads();
#pragma unroll 4
        for (int kk = 0; kk < 32; ++kk) {
            int k = t * 32 + kk;
            float av[8];
#pragma unroll
            for (int r = 0; r < 8; r++) av[r] = Hs[k * NM + row0 + r];
            float4 b0 = *(const float4*)&Bs[kk * NM + col0b];
            float bv[4] = {b0.x, b0.y, b0.z, b0.w};
#pragma unroll
            for (int r = 0; r < 8; r++)
#pragma unroll
                for (int c = 0; c < 4; c++) acc2[r][c] += av[r] * bv[c];
        }
        __syncthreads();
    }
#pragma unroll
    for (int r = 0; r < 8; r++)
#pragma unroll
        for (int c = 0; c < 4; c++)
            Hs[(col0b + c) * NM + row0 + r] = silu_m(acc2[r][c] + sb2[col0b + c]);
    __syncthreads();

    // GEMM3 (K=64, 9 cols): 2 threads per node
    {
        const int nd = tid >> 1;
        const int half = tid & 1;
        const int cbase = half * 5;
        const int ncols = half ? 4 : 5;
        float a3[5];
#pragma unroll
        for (int j = 0; j < 5; j++) a3[j] = 0.0f;
        for (int k = 0; k < 64; k++) {
            float tv = Hs[k * NM + nd];
#pragma unroll
            for (int j = 0; j < 5; j++)
                if (j < ncols) a3[j] += tv * w3s[k * FOUT + cbase + j];
        }
        int node = n0 + nd;
        if (node < NN) {
            for (int j = 0; j < ncols; j++)
                out[(size_t)node * FOUT + cbase + j] = a3[j] + sb3[cbase + j];
        }
    }
}

// ---------------- launch ----------------
extern "C" void kernel_launch(void* const* d_in, const int* in_sizes, int n_in,
                              void* d_out, int out_size) {
    const float* x      = (const float*)d_in[0];
    const void*  ei     = d_in[1];
    const float* ea     = (const float*)d_in[2];
    const float* enc_w1 = (const float*)d_in[3];
    const float* enc_b1 = (const float*)d_in[4];
    const float* enc_w2 = (const float*)d_in[5];
    const float* enc_b2 = (const float*)d_in[6];
    const float* conv_w1 = (const float*)d_in[7];
    const float* conv_b1 = (const float*)d_in[8];
    const float* conv_w2 = (const float*)d_in[9];
    const float* conv_b2 = (const float*)d_in[10];
    const float* dec_w1 = (const float*)d_in[11];
    const float* dec_b1 = (const float*)d_in[12];
    const float* dec_w2 = (const float*)d_in[13];
    const float* dec_b2 = (const float*)d_in[14];
    const float* dec_w3 = (const float*)d_in[15];
    const float* dec_b3 = (const float*)d_in[16];

    cudaFuncSetAttribute(k_encoder2, cudaFuncAttributeMaxDynamicSharedMemorySize, EN_SMEM);
    cudaFuncSetAttribute(k_nodemlp, cudaFuncAttributeMaxDynamicSharedMemorySize, NM_SMEM);
    cudaFuncSetAttribute(k_decoder2, cudaFuncAttributeMaxDynamicSharedMemorySize, DE_SMEM);

    k_detect<<<1, 256>>>((const int*)ei);
    k_init<<<(NN + 255) / 256, 256>>>();
    k_convert<<<(EE + 255) / 256, 256>>>(ei);
    k_invdeg<<<(NN + 255) / 256, 256>>>();
    k_scan<<<1, 1024>>>();
    k_scatter<<<(EE + 255) / 256, 256>>>(ea);

    const int nTiles = (NN + 127) / 128;  // 157
    k_encoder2<<<nTiles, 256, EN_SMEM>>>(x, enc_w1, enc_b1, enc_w2, enc_b2);
    k_nodeproj<<<nTiles * 2, 256>>>(conv_w1);   // P for layer 0

    for (int l = 0; l < NLAYERS; l++) {
        k_edgesum<<<(NN + 7) / 8, 256>>>(conv_w1 + (size_t)l * 259 * H,
                                         conv_b1 + (size_t)l * H);
        k_nodemlp<<<nTiles, 256, NM_SMEM>>>(conv_w2 + (size_t)l * H * H,
                                            conv_b2 + (size_t)l * H,
                                            conv_w1 + (size_t)(l + 1) * 259 * H,
                                            (l + 1 < NLAYERS) ? 1 : 0);
    }

    k_decoder2<<<nTiles, 256, DE_SMEM>>>(dec_w1, dec_b1, dec_w2, dec_b2,
                                         dec_w3, dec_b3, (float*)d_out);
}

// round 10
// speedup vs baseline: 10.2840x; 1.6554x over previous
#include <cuda_runtime.h>
#include <cuda_bf16.h>
#include <cstdint>

#define NN 20000
#define EE 320000
#define H 128
#define FIN 14
#define FOUT 9
#define NLAYERS 6
#define NM 132
#define ASTR 136          // bf16 operand row stride (elems) -> 272 B

#define MD_PROJ 0
#define MD_BOTH 1
#define MD_AGG  2

// ---------------- device scratch ----------------
__device__ float g_h[NN * H];
__device__ float g_zsum[NN * H];
__device__ float g_P[NN * 256];
__device__ float g_invdeg[NN];
__device__ int   g_src[EE];
__device__ int   g_dst[EE];
__device__ int   g_cnt[NN];
__device__ int   g_off[NN + 1];
__device__ int   g_ssrc[EE];
__device__ float4 g_sea[EE];
__device__ int   g_is64;
// prebuilt B-operand images (transposed, padded, hi/lo)
__device__ __align__(16) __nv_bfloat16 g_W2h[NLAYERS * H * ASTR];
__device__ __align__(16) __nv_bfloat16 g_W2l[NLAYERS * H * ASTR];
__device__ __align__(16) __nv_bfloat16 g_W1h[NLAYERS * 256 * ASTR];
__device__ __align__(16) __nv_bfloat16 g_W1l[NLAYERS * 256 * ASTR];

__device__ __forceinline__ float silu_m(float x) {
    return __fdividef(x, 1.0f + __expf(-x));
}

__device__ __forceinline__ uint32_t smem_u32(const void* p) {
    uint32_t a;
    asm("{ .reg .u64 t; cvta.to.shared.u64 t, %1; cvt.u32.u64 %0, t; }" : "=r"(a) : "l"(p));
    return a;
}

__device__ __forceinline__ void ldsm4(uint32_t* r, uint32_t addr) {
    asm volatile("ldmatrix.sync.aligned.m8n8.x4.shared.b16 {%0,%1,%2,%3}, [%4];"
                 : "=r"(r[0]), "=r"(r[1]), "=r"(r[2]), "=r"(r[3]) : "r"(addr));
}

__device__ __forceinline__ void mma16816(float* d, const uint32_t* a,
                                         uint32_t b0, uint32_t b1) {
    asm volatile(
        "mma.sync.aligned.m16n8k16.row.col.f32.bf16.bf16.f32 "
        "{%0,%1,%2,%3}, {%4,%5,%6,%7}, {%8,%9}, {%0,%1,%2,%3};"
        : "+f"(d[0]), "+f"(d[1]), "+f"(d[2]), "+f"(d[3])
        : "r"(a[0]), "r"(a[1]), "r"(a[2]), "r"(a[3]), "r"(b0), "r"(b1));
}

__device__ __forceinline__ uint32_t pack_bf16x2(float a, float b) {
    __nv_bfloat162 t;
    t.x = __float2bfloat16_rn(a);
    t.y = __float2bfloat16_rn(b);
    return *(uint32_t*)&t;
}

// ---------------- preprocessing ----------------
__global__ void k_detect(const int* __restrict__ ei) {
    __shared__ int cnt;
    if (threadIdx.x == 0) cnt = 0;
    __syncthreads();
    int c = 0;
    for (int i = threadIdx.x; i < 1024; i += 256)
        if (ei[2 * i + 1] != 0) c++;
    if (c) atomicAdd(&cnt, c);
    __syncthreads();
    if (threadIdx.x == 0) g_is64 = (cnt == 0) ? 1 : 0;
}

__global__ void k_init() {
    int i = blockIdx.x * blockDim.x + threadIdx.x;
    if (i < NN) g_cnt[i] = 0;
}

__global__ void k_convert(const void* __restrict__ ei) {
    int i = blockIdx.x * blockDim.x + threadIdx.x;
    if (i >= EE) return;
    int s, d;
    if (g_is64) {
        const long long* p = (const long long*)ei;
        s = (int)p[i];
        d = (int)p[EE + i];
    } else {
        const int* p = (const int*)ei;
        s = p[i];
        d = p[EE + i];
    }
    g_src[i] = s;
    g_dst[i] = d;
    atomicAdd(&g_cnt[d], 1);
}

__global__ void k_invdeg() {
    int i = blockIdx.x * blockDim.x + threadIdx.x;
    if (i < NN) g_invdeg[i] = 1.0f / fmaxf((float)g_cnt[i], 1.0f);
}

__global__ void k_scan() {
    __shared__ int wsum[32];
    __shared__ int carry;
    const int lane = threadIdx.x & 31;
    const int wp = threadIdx.x >> 5;
    if (threadIdx.x == 0) carry = 0;
    __syncthreads();
    for (int base = 0; base < NN; base += 1024) {
        int i = base + threadIdx.x;
        int v = (i < NN) ? g_cnt[i] : 0;
        int s = v;
#pragma unroll
        for (int dlt = 1; dlt < 32; dlt <<= 1) {
            int t = __shfl_up_sync(0xFFFFFFFFu, s, dlt);
            if (lane >= dlt) s += t;
        }
        __syncthreads();
        if (lane == 31) wsum[wp] = s;
        __syncthreads();
        if (wp == 0) {
            int ws = wsum[lane];
#pragma unroll
            for (int dlt = 1; dlt < 32; dlt <<= 1) {
                int t = __shfl_up_sync(0xFFFFFFFFu, ws, dlt);
                if (lane >= dlt) ws += t;
            }
            wsum[lane] = ws;
        }
        __syncthreads();
        int excl = carry + s - v + (wp > 0 ? wsum[wp - 1] : 0);
        if (i < NN) { g_off[i] = excl; g_cnt[i] = 0; }
        __syncthreads();
        if (threadIdx.x == 0) carry += wsum[31];
    }
    if (threadIdx.x == 0) g_off[NN] = EE;
}

__global__ void k_scatter(const float* __restrict__ ea) {
    int e = blockIdx.x * blockDim.x + threadIdx.x;
    if (e >= EE) return;
    int d = g_dst[e];
    int pos = g_off[d] + atomicAdd(&g_cnt[d], 1);
    g_ssrc[pos] = g_src[e];
    float4 v;
    v.x = ea[e * 3 + 0];
    v.y = ea[e * 3 + 1];
    v.z = ea[e * 3 + 2];
    v.w = 0.0f;
    g_sea[pos] = v;
}

// ---------------- weight image prep ----------------
__global__ void k_prepw2(const float* __restrict__ W2) {
    int i = blockIdx.x * 256 + threadIdx.x;      // 6*16384
    int l = i >> 14, r = i & 16383, n = r >> 7, k = r & 127;
    float w = W2[(size_t)l * 16384 + k * H + n];
    __nv_bfloat16 hi = __float2bfloat16_rn(w);
    __nv_bfloat16 lo = __float2bfloat16_rn(w - __bfloat162float(hi));
    size_t off = (size_t)l * H * ASTR + n * ASTR + k;
    g_W2h[off] = hi;
    g_W2l[off] = lo;
}

__global__ void k_prepw1(const float* __restrict__ W1) {
    int i = blockIdx.x * 256 + threadIdx.x;      // 6*32768
    int l = i >> 15, r = i & 32767, n = r >> 7, k = r & 127;
    int row = ((n >> 7) << 7) + k;               // n<128 -> k ; n>=128 -> 128+k
    float w = W1[(size_t)l * 259 * H + row * H + (n & 127)];
    __nv_bfloat16 hi = __float2bfloat16_rn(w);
    __nv_bfloat16 lo = __float2bfloat16_rn(w - __bfloat162float(hi));
    size_t off = (size_t)l * 256 * ASTR + n * ASTR + k;
    g_W1h[off] = hi;
    g_W1l[off] = lo;
}

// ---------------- tiled encoder ----------------
#define EN_XS 0
#define EN_W1 (EN_XS + FIN * NM * 4)
#define EN_TS (EN_W1 + FIN * H * 4)
#define EN_BS (EN_TS + H * NM * 4)
#define EN_B1 (EN_BS + 32 * NM * 4)
#define EN_B2 (EN_B1 + 512)
#define EN_SMEM (EN_B2 + 512)

__global__ void __launch_bounds__(256, 2)
k_encoder2(const float* __restrict__ x,
           const float* __restrict__ w1, const float* __restrict__ b1,
           const float* __restrict__ w2, const float* __restrict__ b2) {
    extern __shared__ char smb[];
    float* Xs  = (float*)(smb + EN_XS);
    float* W1s = (float*)(smb + EN_W1);
    float* Ts  = (float*)(smb + EN_TS);
    float* Bs  = (float*)(smb + EN_BS);
    float* sB1 = (float*)(smb + EN_B1);
    float* sB2 = (float*)(smb + EN_B2);
    const int n0 = blockIdx.x * 128;
    const int tid = threadIdx.x;
    const int tx = tid & 15, ty = tid >> 4;
    const int row0 = ty * 8, col0 = tx * 8;

    for (int i = tid; i < FIN * 128; i += 256) {
        int k = i >> 7, nd = i & 127;
        Xs[k * NM + nd] = (n0 + nd < NN) ? x[(size_t)(n0 + nd) * FIN + k] : 0.0f;
        W1s[i] = w1[i];
    }
    if (tid < 128) { sB1[tid] = b1[tid]; sB2[tid] = b2[tid]; }
    __syncthreads();

    {
        float acc[8][8];
#pragma unroll
        for (int r = 0; r < 8; r++)
#pragma unroll
            for (int c = 0; c < 8; c++) acc[r][c] = 0.0f;
#pragma unroll
        for (int k = 0; k < FIN; k++) {
            float av[8], bv[8];
#pragma unroll
            for (int r = 0; r < 8; r++) av[r] = Xs[k * NM + row0 + r];
#pragma unroll
            for (int c = 0; c < 8; c++) bv[c] = W1s[k * 128 + col0 + c];
#pragma unroll
            for (int r = 0; r < 8; r++)
#pragma unroll
                for (int c = 0; c < 8; c++) acc[r][c] += av[r] * bv[c];
        }
#pragma unroll
        for (int r = 0; r < 8; r++)
#pragma unroll
            for (int c = 0; c < 8; c++)
                Ts[(col0 + c) * NM + row0 + r] = silu_m(acc[r][c] + sB1[col0 + c]);
    }
    __syncthreads();

    {
        float acc[8][8];
#pragma unroll
        for (int r = 0; r < 8; r++)
#pragma unroll
            for (int c = 0; c < 8; c++) acc[r][c] = 0.0f;
        for (int t = 0; t < 4; t++) {
#pragma unroll
            for (int it = 0; it < 4; ++it) {
                int i = tid + it * 256;
                int rowk = i >> 5, c4 = i & 31;
                *(float4*)&Bs[rowk * NM + c4 * 4] =
                    *(const float4*)&w2[(size_t)(t * 32 + rowk) * H + c4 * 4];
            }
            __syncthreads();
#pragma unroll 4
            for (int kk = 0; kk < 32; ++kk) {
                float av[8], bv[8];
                int k = t * 32 + kk;
#pragma unroll
                for (int r = 0; r < 8; r++) av[r] = Ts[k * NM + row0 + r];
                float4 b0 = *(const float4*)&Bs[kk * NM + col0];
                float4 b1v = *(const float4*)&Bs[kk * NM + col0 + 4];
                bv[0] = b0.x; bv[1] = b0.y; bv[2] = b0.z; bv[3] = b0.w;
                bv[4] = b1v.x; bv[5] = b1v.y; bv[6] = b1v.z; bv[7] = b1v.w;
#pragma unroll
                for (int r = 0; r < 8; r++)
#pragma unroll
                    for (int c = 0; c < 8; c++) acc[r][c] += av[r] * bv[c];
            }
            __syncthreads();
        }
#pragma unroll
        for (int r = 0; r < 8; r++) {
            int node = n0 + row0 + r;
            if (node < NN) {
                float* hp = &g_h[(size_t)node * H + col0];
                *(float4*)hp = make_float4(acc[r][0] + sB2[col0 + 0], acc[r][1] + sB2[col0 + 1],
                                           acc[r][2] + sB2[col0 + 2], acc[r][3] + sB2[col0 + 3]);
                *(float4*)(hp + 4) = make_float4(acc[r][4] + sB2[col0 + 4], acc[r][5] + sB2[col0 + 5],
                                                 acc[r][6] + sB2[col0 + 6], acc[r][7] + sB2[col0 + 7]);
            }
        }
    }
}

// ---------------- CSR edge sum ----------------
__global__ void __launch_bounds__(256)
k_edgesum(const float* __restrict__ W1, const float* __restrict__ b1) {
    const int node = blockIdx.x * 8 + (threadIdx.x >> 5);
    if (node >= NN) return;
    const int lid = threadIdx.x & 31;
    const int c = lid * 4;
    const float4 wa = *(const float4*)&W1[256 * H + c];
    const float4 wb = *(const float4*)&W1[257 * H + c];
    const float4 wc = *(const float4*)&W1[258 * H + c];
    const float4 bb = *(const float4*)&b1[c];
    const float4 pa = *(const float4*)&g_P[(size_t)node * 256 + c];
    const float bx = pa.x + bb.x, by = pa.y + bb.y;
    const float bz = pa.z + bb.z, bw = pa.w + bb.w;
    float4 acc = make_float4(0.f, 0.f, 0.f, 0.f);
    int e = g_off[node];
    const int end = g_off[node + 1];
    if (e < end) {
        int src = g_ssrc[e];
        float4 eav = g_sea[e];
        float4 pb = *(const float4*)&g_P[(size_t)src * 256 + 128 + c];
        while (e < end) {
            const int en = e + 1;
            int srcN = src; float4 eavN = eav; float4 pbN = pb;
            if (en < end) {
                srcN = g_ssrc[en];
                eavN = g_sea[en];
                pbN = *(const float4*)&g_P[(size_t)srcN * 256 + 128 + c];
            }
            float v0 = bx + pb.x + eav.x * wa.x + eav.y * wb.x + eav.z * wc.x;
            float v1 = by + pb.y + eav.x * wa.y + eav.y * wb.y + eav.z * wc.y;
            float v2 = bz + pb.z + eav.x * wa.z + eav.y * wb.z + eav.z * wc.z;
            float v3 = bw + pb.w + eav.x * wa.w + eav.y * wb.w + eav.z * wc.w;
            acc.x += silu_m(v0);
            acc.y += silu_m(v1);
            acc.z += silu_m(v2);
            acc.w += silu_m(v3);
            e = en; src = srcN; eav = eavN; pb = pbN;
        }
    }
    const float iv = g_invdeg[node];
    acc.x *= iv; acc.y *= iv; acc.z *= iv; acc.w *= iv;
    *(float4*)&g_zsum[(size_t)node * H + c] = acc;
}

// ---------------- HMMA nodemlp: agg GEMM + residual + projection ---------
#define NB_AH 0
#define NB_AL 17408
#define NB_BH 34816
#define NB_BL 69632
#define NB_B2 104448
#define NB_MK 104960
#define NB_SMEM 105216

// warp-tile mma: 32 rows x 32 cols, 3-term bf16
__device__ __forceinline__ void mma_tile(uint32_t aH, uint32_t aL,
                                         uint32_t bH, uint32_t bL,
                                         int mrow, int ncol, int lid,
                                         float d[2][4][4]) {
    const int a_r = lid & 15, a_c8 = (lid >> 4) * 8;
    const int b_g = lid >> 3;
    const int b_n = (b_g >> 1) * 8 + (lid & 7);
    const int b_c8 = (b_g & 1) * 8;
#pragma unroll 1
    for (int ks = 0; ks < 8; ks++) {
        const int k0 = ks * 16;
        uint32_t ah[2][4], al[2][4];
#pragma unroll
        for (int mt = 0; mt < 2; mt++) {
            uint32_t addr = aH + (uint32_t)(mrow + mt * 16 + a_r) * 272
                          + (uint32_t)(k0 + a_c8) * 2;
            ldsm4(ah[mt], addr);
            ldsm4(al[mt], addr + (aL - aH));
        }
#pragma unroll
        for (int bt = 0; bt < 2; bt++) {
            uint32_t bh[4], bl[4];
            uint32_t addr = bH + (uint32_t)(ncol + bt * 16 + b_n) * 272
                          + (uint32_t)(k0 + b_c8) * 2;
            ldsm4(bh, addr);
            ldsm4(bl, addr + (bL - bH));
            const int nt0 = bt * 2, nt1 = nt0 + 1;
#pragma unroll
            for (int mt = 0; mt < 2; mt++) {
                mma16816(d[mt][nt0], ah[mt], bh[0], bh[1]);
                mma16816(d[mt][nt1], ah[mt], bh[2], bh[3]);
                mma16816(d[mt][nt0], ah[mt], bl[0], bl[1]);
                mma16816(d[mt][nt1], ah[mt], bl[2], bl[3]);
                mma16816(d[mt][nt0], al[mt], bh[0], bh[1]);
                mma16816(d[mt][nt1], al[mt], bh[2], bh[3]);
            }
        }
    }
}

__global__ void __launch_bounds__(256, 2)
k_nodemlp(int layer, const float* __restrict__ b2, int mode) {
    extern __shared__ char smb[];
    const uint32_t sb = smem_u32(smb);
    float* sB2 = (float*)(smb + NB_B2);
    float* sMk = (float*)(smb + NB_MK);
    const int tid = threadIdx.x;
    const int lid = tid & 31;
    const int wid = tid >> 5;
    const int n0 = blockIdx.x * 64;
    const int mrow = (wid & 1) * 32;
    const int ncol = (wid >> 1) * 32;
    const int fr = lid >> 2, fc = (lid & 3) * 2;

    if (mode != MD_PROJ) {
        if (tid < 128) sB2[tid] = b2[tid];
        if (tid < 64) {
            int node = n0 + tid;
            sMk[tid] = (node < NN && g_cnt[node] > 0) ? 1.0f : 0.0f;
        }
        // convert zsum tile -> As hi/lo   (FIX: byte offset = seg*8, not seg*16)
#pragma unroll
        for (int it = 0; it < 8; ++it) {
            int i = tid + it * 256;
            int nd = i >> 5, seg = i & 31;
            int node = n0 + nd;
            float4 v = make_float4(0.f, 0.f, 0.f, 0.f);
            if (node < NN) v = *(const float4*)&g_zsum[(size_t)node * H + seg * 4];
            __nv_bfloat16 h0 = __float2bfloat16_rn(v.x), h1 = __float2bfloat16_rn(v.y);
            __nv_bfloat16 h2 = __float2bfloat16_rn(v.z), h3 = __float2bfloat16_rn(v.w);
            uint2 uh, ul;
            uh.x = pack_bf16x2(v.x, v.y);
            uh.y = pack_bf16x2(v.z, v.w);
            ul.x = pack_bf16x2(v.x - __bfloat162float(h0), v.y - __bfloat162float(h1));
            ul.y = pack_bf16x2(v.z - __bfloat162float(h2), v.w - __bfloat162float(h3));
            *(uint2*)(smb + NB_AH + nd * 272 + seg * 8) = uh;
            *(uint2*)(smb + NB_AL + nd * 272 + seg * 8) = ul;
        }
        // load W2 image
        {
            const uint4* srcH = (const uint4*)(g_W2h + (size_t)layer * H * ASTR);
            const uint4* srcL = (const uint4*)(g_W2l + (size_t)layer * H * ASTR);
            uint4* dstH = (uint4*)(smb + NB_BH);
            uint4* dstL = (uint4*)(smb + NB_BL);
            for (int i = tid; i < 2176; i += 256) { dstH[i] = srcH[i]; dstL[i] = srcL[i]; }
        }
        __syncthreads();

        float d[2][4][4];
#pragma unroll
        for (int mt = 0; mt < 2; mt++)
#pragma unroll
            for (int nt = 0; nt < 4; nt++)
#pragma unroll
                for (int q = 0; q < 4; q++) d[mt][nt][q] = 0.0f;
        mma_tile(sb + NB_AH, sb + NB_AL, sb + NB_BH, sb + NB_BL, mrow, ncol, lid, d);
        __syncthreads();

        // epilogue: h_new = h + D + b2*mask -> g_h (+ As hi/lo if BOTH)
#pragma unroll
        for (int mt = 0; mt < 2; mt++) {
#pragma unroll
            for (int nt = 0; nt < 4; nt++) {
                int c = ncol + nt * 8 + fc;
#pragma unroll
                for (int half8 = 0; half8 < 2; half8++) {
                    int r = mrow + mt * 16 + fr + half8 * 8;
                    int node = n0 + r;
                    float d0 = d[mt][nt][half8 * 2 + 0];
                    float d1 = d[mt][nt][half8 * 2 + 1];
                    float hn0 = 0.f, hn1 = 0.f;
                    if (node < NN) {
                        float mk = sMk[r];
                        float2 hv = *(const float2*)&g_h[(size_t)node * H + c];
                        hn0 = hv.x + d0 + sB2[c] * mk;
                        hn1 = hv.y + d1 + sB2[c + 1] * mk;
                        *(float2*)&g_h[(size_t)node * H + c] = make_float2(hn0, hn1);
                    }
                    if (mode == MD_BOTH) {
                        __nv_bfloat16 b0 = __float2bfloat16_rn(hn0);
                        __nv_bfloat16 b1v = __float2bfloat16_rn(hn1);
                        *(uint32_t*)(smb + NB_AH + r * 272 + c * 2) = pack_bf16x2(hn0, hn1);
                        *(uint32_t*)(smb + NB_AL + r * 272 + c * 2) =
                            pack_bf16x2(hn0 - __bfloat162float(b0), hn1 - __bfloat162float(b1v));
                    }
                }
            }
        }
        if (mode == MD_AGG) return;
    } else {
        // PROJ: convert g_h tile -> As hi/lo   (FIX: seg*8)
#pragma unroll
        for (int it = 0; it < 8; ++it) {
            int i = tid + it * 256;
            int nd = i >> 5, seg = i & 31;
            int node = n0 + nd;
            float4 v = make_float4(0.f, 0.f, 0.f, 0.f);
            if (node < NN) v = *(const float4*)&g_h[(size_t)node * H + seg * 4];
            __nv_bfloat16 h0 = __float2bfloat16_rn(v.x), h1 = __float2bfloat16_rn(v.y);
            __nv_bfloat16 h2 = __float2bfloat16_rn(v.z), h3 = __float2bfloat16_rn(v.w);
            uint2 uh, ul;
            uh.x = pack_bf16x2(v.x, v.y);
            uh.y = pack_bf16x2(v.z, v.w);
            ul.x = pack_bf16x2(v.x - __bfloat162float(h0), v.y - __bfloat162float(h1));
            ul.y = pack_bf16x2(v.z - __bfloat162float(h2), v.w - __bfloat162float(h3));
            *(uint2*)(smb + NB_AH + nd * 272 + seg * 8) = uh;
            *(uint2*)(smb + NB_AL + nd * 272 + seg * 8) = ul;
        }
    }

    // phase B: P = h_new @ [W1a | W1b] of layer lw (2 N-halves of 128)
    const int lw = (mode == MD_PROJ) ? 0 : layer + 1;
    for (int half = 0; half < 2; half++) {
        {
            const uint4* srcH = (const uint4*)(g_W1h + (size_t)(lw * 256 + half * 128) * ASTR);
            const uint4* srcL = (const uint4*)(g_W1l + (size_t)(lw * 256 + half * 128) * ASTR);
            uint4* dstH = (uint4*)(smb + NB_BH);
            uint4* dstL = (uint4*)(smb + NB_BL);
            for (int i = tid; i < 2176; i += 256) { dstH[i] = srcH[i]; dstL[i] = srcL[i]; }
        }
        __syncthreads();

        float d[2][4][4];
#pragma unroll
        for (int mt = 0; mt < 2; mt++)
#pragma unroll
            for (int nt = 0; nt < 4; nt++)
#pragma unroll
                for (int q = 0; q < 4; q++) d[mt][nt][q] = 0.0f;
        mma_tile(sb + NB_AH, sb + NB_AL, sb + NB_BH, sb + NB_BL, mrow, ncol, lid, d);

#pragma unroll
        for (int mt = 0; mt < 2; mt++) {
#pragma unroll
            for (int nt = 0; nt < 4; nt++) {
                int c = ncol + nt * 8 + fc;
#pragma unroll
                for (int half8 = 0; half8 < 2; half8++) {
                    int r = mrow + mt * 16 + fr + half8 * 8;
                    int node = n0 + r;
                    if (node < NN) {
                        *(float2*)&g_P[(size_t)node * 256 + half * 128 + c] =
                            make_float2(d[mt][nt][half8 * 2 + 0], d[mt][nt][half8 * 2 + 1]);
                    }
                }
            }
        }
        __syncthreads();
    }
}

// ---------------- tiled decoder ----------------
#define DE_HS 0
#define DE_BS (DE_HS + 128 * NM * 4)
#define DE_W3 (DE_BS + 32 * NM * 4)
#define DE_B1 (DE_W3 + 64 * FOUT * 4)
#define DE_B2 (DE_B1 + 512)
#define DE_B3 (DE_B2 + 256)
#define DE_SMEM (DE_B3 + 64)

__global__ void __launch_bounds__(256, 2)
k_decoder2(const float* __restrict__ w1, const float* __restrict__ b1,
           const float* __restrict__ w2, const float* __restrict__ b2,
           const float* __restrict__ w3, const float* __restrict__ b3,
           float* __restrict__ out) {
    extern __shared__ char smb[];
    float* Hs  = (float*)(smb + DE_HS);
    float* Bs  = (float*)(smb + DE_BS);
    float* w3s = (float*)(smb + DE_W3);
    float* sb1 = (float*)(smb + DE_B1);
    float* sb2 = (float*)(smb + DE_B2);
    float* sb3 = (float*)(smb + DE_B3);
    const int n0 = blockIdx.x * 128;
    const int tid = threadIdx.x;
    const int tx = tid & 15, ty = tid >> 4;
    const int row0 = ty * 8, col0 = tx * 8;

#pragma unroll
    for (int it = 0; it < 16; ++it) {
        int i = tid + it * 256;
        int nd = i >> 5, seg = i & 31;
        int node = n0 + nd;
        float4 v = make_float4(0.f, 0.f, 0.f, 0.f);
        if (node < NN) v = *(const float4*)&g_h[(size_t)node * H + seg * 4];
        Hs[(seg * 4 + 0) * NM + nd] = v.x;
        Hs[(seg * 4 + 1) * NM + nd] = v.y;
        Hs[(seg * 4 + 2) * NM + nd] = v.z;
        Hs[(seg * 4 + 3) * NM + nd] = v.w;
    }
    for (int i = tid; i < 64 * FOUT; i += 256) w3s[i] = w3[i];
    if (tid < 128) sb1[tid] = b1[tid];
    if (tid < 64) sb2[tid] = b2[tid];
    if (tid < FOUT) sb3[tid] = b3[tid];
    __syncthreads();

    float acc[8][8];
#pragma unroll
    for (int r = 0; r < 8; r++)
#pragma unroll
        for (int c = 0; c < 8; c++) acc[r][c] = 0.0f;
    for (int t = 0; t < 4; t++) {
#pragma unroll
        for (int it = 0; it < 4; ++it) {
            int i = tid + it * 256;
            int rowk = i >> 5, c4 = i & 31;
            *(float4*)&Bs[rowk * NM + c4 * 4] =
                *(const float4*)&w1[(size_t)(t * 32 + rowk) * H + c4 * 4];
        }
        __syncthreads();
#pragma unroll 4
        for (int kk = 0; kk < 32; ++kk) {
            int k = t * 32 + kk;
            float av[8], bv[8];
#pragma unroll
            for (int r = 0; r < 8; r++) av[r] = Hs[k * NM + row0 + r];
            float4 b0 = *(const float4*)&Bs[kk * NM + col0];
            float4 b1v = *(const float4*)&Bs[kk * NM + col0 + 4];
            bv[0] = b0.x; bv[1] = b0.y; bv[2] = b0.z; bv[3] = b0.w;
            bv[4] = b1v.x; bv[5] = b1v.y; bv[6] = b1v.z; bv[7] = b1v.w;
#pragma unroll
            for (int r = 0; r < 8; r++)
#pragma unroll
                for (int c = 0; c < 8; c++) acc[r][c] += av[r] * bv[c];
        }
        __syncthreads();
    }
#pragma unroll
    for (int r = 0; r < 8; r++)
#pragma unroll
        for (int c = 0; c < 8; c++)
            Hs[(col0 + c) * NM + row0 + r] = silu_m(acc[r][c] + sb1[col0 + c]);
    __syncthreads();

    const int col0b = tx * 4;
    float acc2[8][4];
#pragma unroll
    for (int r = 0; r < 8; r++)
#pragma unroll
        for (int c = 0; c < 4; c++) acc2[r][c] = 0.0f;
    for (int t = 0; t < 4; t++) {
#pragma unroll
        for (int it = 0; it < 2; ++it) {
            int i = tid + it * 256;
            int rowk = i >> 4, c4 = i & 15;
            *(float4*)&Bs[rowk * NM + c4 * 4] =
                *(const float4*)&w2[(size_t)(t * 32 + rowk) * 64 + c4 * 4];
        }
        __syncthreads();
#pragma unroll 4
        for (int kk = 0; kk < 32; ++kk) {
            int k = t * 32 + kk;
            float av[8];
#pragma unroll
            for (int r = 0; r < 8; r++) av[r] = Hs[k * NM + row0 + r];
            float4 b0 = *(const float4*)&Bs[kk * NM + col0b];
            float bv[4] = {b0.x, b0.y, b0.z, b0.w};
#pragma unroll
            for (int r = 0; r < 8; r++)
#pragma unroll
                for (int c = 0; c < 4; c++) acc2[r][c] += av[r] * bv[c];
        }
        __syncthreads();
    }
#pragma unroll
    for (int r = 0; r < 8; r++)
#pragma unroll
        for (int c = 0; c < 4; c++)
            Hs[(col0b + c) * NM + row0 + r] = silu_m(acc2[r][c] + sb2[col0b + c]);
    __syncthreads();

    {
        const int nd = tid >> 1;
        const int half = tid & 1;
        const int cbase = half * 5;
        const int ncols = half ? 4 : 5;
        float a3[5];
#pragma unroll
        for (int j = 0; j < 5; j++) a3[j] = 0.0f;
        for (int k = 0; k < 64; k++) {
            float tv = Hs[k * NM + nd];
#pragma unroll
            for (int j = 0; j < 5; j++)
                if (j < ncols) a3[j] += tv * w3s[k * FOUT + cbase + j];
        }
        int node = n0 + nd;
        if (node < NN) {
            for (int j = 0; j < ncols; j++)
                out[(size_t)node * FOUT + cbase + j] = a3[j] + sb3[cbase + j];
        }
    }
}

// ---------------- launch ----------------
extern "C" void kernel_launch(void* const* d_in, const int* in_sizes, int n_in,
                              void* d_out, int out_size) {
    const float* x      = (const float*)d_in[0];
    const void*  ei     = d_in[1];
    const float* ea     = (const float*)d_in[2];
    const float* enc_w1 = (const float*)d_in[3];
    const float* enc_b1 = (const float*)d_in[4];
    const float* enc_w2 = (const float*)d_in[5];
    const float* enc_b2 = (const float*)d_in[6];
    const float* conv_w1 = (const float*)d_in[7];
    const float* conv_b1 = (const float*)d_in[8];
    const float* conv_w2 = (const float*)d_in[9];
    const float* conv_b2 = (const float*)d_in[10];
    const float* dec_w1 = (const float*)d_in[11];
    const float* dec_b1 = (const float*)d_in[12];
    const float* dec_w2 = (const float*)d_in[13];
    const float* dec_b2 = (const float*)d_in[14];
    const float* dec_w3 = (const float*)d_in[15];
    const float* dec_b3 = (const float*)d_in[16];

    cudaFuncSetAttribute(k_encoder2, cudaFuncAttributeMaxDynamicSharedMemorySize, EN_SMEM);
    cudaFuncSetAttribute(k_nodemlp, cudaFuncAttributeMaxDynamicSharedMemorySize, NB_SMEM);
    cudaFuncSetAttribute(k_decoder2, cudaFuncAttributeMaxDynamicSharedMemorySize, DE_SMEM);

    k_detect<<<1, 256>>>((const int*)ei);
    k_init<<<(NN + 255) / 256, 256>>>();
    k_convert<<<(EE + 255) / 256, 256>>>(ei);
    k_invdeg<<<(NN + 255) / 256, 256>>>();
    k_scan<<<1, 1024>>>();
    k_scatter<<<(EE + 255) / 256, 256>>>(ea);
    k_prepw2<<<(NLAYERS * 128 * 128) / 256, 256>>>(conv_w2);
    k_prepw1<<<(NLAYERS * 256 * 128) / 256, 256>>>(conv_w1);

    const int nTiles = (NN + 127) / 128;   // 157
    const int nT64   = (NN + 63) / 64;     // 313
    k_encoder2<<<nTiles, 256, EN_SMEM>>>(x, enc_w1, enc_b1, enc_w2, enc_b2);
    k_nodemlp<<<nT64, 256, NB_SMEM>>>(0, conv_b2, MD_PROJ);

    for (int l = 0; l < NLAYERS; l++) {
        k_edgesum<<<(NN + 7) / 8, 256>>>(conv_w1 + (size_t)l * 259 * H,
                                         conv_b1 + (size_t)l * H);
        k_nodemlp<<<nT64, 256, NB_SMEM>>>(l, conv_b2 + (size_t)l * H,
                                          (l + 1 < NLAYERS) ? MD_BOTH : MD_AGG);
    }

    k_decoder2<<<nTiles, 256, DE_SMEM>>>(dec_w1, dec_b1, dec_w2, dec_b2,
                                         dec_w3, dec_b3, (float*)d_out);
}